// round 14
// baseline (speedup 1.0000x reference)
#include <cuda_runtime.h>
#include <cuda_bf16.h>

#define NN 50000
#define EE 1600000
#define DD 32
#define NLAYERS 8
#define TOPK 8
#define VOCAB 100

// ---------------- device scratch (static, no allocations) ----------------
__device__ float g_hi[NN*DD];
__device__ float g_hj[NN*DD];
__device__ float g_hn[NN*DD];
__device__ float g_h [NN*DD];
// e/f in MMA C-fragment order (f32) per 16-edge tile
__device__ float4 g_e[EE*8];
__device__ float4 g_f[EE*8];
__device__ float g_w[EE];          // per-edge softmax weight exp(logit)
__device__ int   g_srcS[EE];
__device__ int   g_dstS[EE];
__device__ int   g_etokS[EE];
__device__ int   g_hist[NN];       // static zero-init; re-zeroed by k_scan each call
__device__ int   g_row [NN+1];
__device__ int   g_cursor[NN];
__device__ float g_rowmax[NN];

__device__ __forceinline__ unsigned f2tf32(float x) {
    unsigned r;
    asm("cvt.rna.tf32.f32 %0, %1;" : "=r"(r) : "f"(x));
    return r;
}

// truncation split: BIG = low-13-bits-masked (exact tf32), SMALL = exact residual
#define SPLITT(F, B, S) do {                                         \
    unsigned _b = __float_as_uint(F) & 0xffffe000u;                  \
    (B) = _b;                                                        \
    (S) = __float_as_uint((F) - __uint_as_float(_b));                \
} while (0)

#define MMA_TF32(ACC, A0, A1, A2, A3, B0, B1)                                   \
    asm volatile("mma.sync.aligned.m16n8k8.row.col.f32.tf32.tf32.f32 "          \
                 "{%0,%1,%2,%3}, {%4,%5,%6,%7}, {%8,%9}, {%0,%1,%2,%3};"        \
                 : "+f"(ACC[0]), "+f"(ACC[1]), "+f"(ACC[2]), "+f"(ACC[3])       \
                 : "r"(A0), "r"(A1), "r"(A2), "r"(A3), "r"(B0), "r"(B1))

#define EB 6250   // edge blocks (256 thr)
#define WB 6250   // node warp-blocks (8 nodes per 256-thr block)

// transposed weight staging: wT[m][c][k] = W[k*32+c], row padded to 36
// lane c reads its column as 8 conflict-free LDS.128
__device__ __forceinline__ void stage_wT(const float* Wni, const float* Wnj,
                                         const float* Wn, const float* b,
                                         float (*wT)[32][36], float* bs, int tid) {
    for (int i = tid; i < 1024; i += 256) {
        int r = i >> 5, c = i & 31;
        wT[0][c][r] = Wni[i];
        wT[1][c][r] = Wnj[i];
        wT[2][c][r] = Wn[i];
    }
    if (tid < 32) bs[tid] = b[tid];
}

__device__ __forceinline__ void proj3(float hv, int lane, float (*wT)[32][36],
                                      const float* bs, float& ai, float& aj, float& an) {
    const float4* wri = (const float4*)wT[0][lane];
    const float4* wrj = (const float4*)wT[1][lane];
    const float4* wrn = (const float4*)wT[2][lane];
    ai = bs[lane]; aj = 0.f; an = 0.f;
#pragma unroll
    for (int q = 0; q < 8; q++) {
        float4 a4 = wri[q], b4 = wrj[q], c4 = wrn[q];
        float h0 = __shfl_sync(0xffffffffu, hv, 4 * q + 0);
        float h1 = __shfl_sync(0xffffffffu, hv, 4 * q + 1);
        float h2 = __shfl_sync(0xffffffffu, hv, 4 * q + 2);
        float h3 = __shfl_sync(0xffffffffu, hv, 4 * q + 3);
        ai += h0 * a4.x + h1 * a4.y + h2 * a4.z + h3 * a4.w;
        aj += h0 * b4.x + h1 * b4.y + h2 * b4.z + h3 * b4.w;
        an += h0 * c4.x + h1 * c4.y + h2 * c4.z + h3 * c4.w;
    }
}

// ---------------- launch 1: hist (blocks 0..EB-1) + init_proj ----------------
__global__ void k_hist_init(const int* __restrict__ dst,
                            const int* __restrict__ h_tok, const float* __restrict__ tok_emb,
                            const float* __restrict__ Wni, const float* __restrict__ Wnj,
                            const float* __restrict__ Wn, const float* __restrict__ b) {
    if (blockIdx.x < EB) {
        int i = blockIdx.x * 256 + threadIdx.x;
        if (i < EE) atomicAdd(&g_hist[dst[i]], 1);
        return;
    }
    __shared__ float wT[3][32][36];
    __shared__ float bs[32];
    int tid = threadIdx.x;
    stage_wT(Wni, Wnj, Wn, b, wT, bs, tid);
    __syncthreads();
    int node = (blockIdx.x - EB) * 8 + (tid >> 5);
    int lane = tid & 31;
    if (node >= NN) return;
    float hv = fmaxf(tok_emb[h_tok[node] * DD + lane], 0.f);
    float ai, aj, an;
    proj3(hv, lane, wT, bs, ai, aj, an);
    g_hi[node * DD + lane] = ai;
    g_hj[node * DD + lane] = aj;
    g_hn[node * DD + lane] = an;
}

// ---------------- launch 2: scan ----------------
__global__ void k_scan() {
    __shared__ int sm[1024];
    int t = threadIdx.x;
    const int CH = (NN + 1023) / 1024;
    int b0 = t * CH;
    int b1 = min(b0 + CH, NN);
    int sum = 0;
    for (int i = b0; i < b1; i++) sum += g_hist[i];
    sm[t] = sum;
    __syncthreads();
    for (int off = 1; off < 1024; off <<= 1) {
        int v = (t >= off) ? sm[t - off] : 0;
        __syncthreads();
        sm[t] += v;
        __syncthreads();
    }
    int pre = sm[t] - sum;
    for (int i = b0; i < b1; i++) {
        g_row[i] = pre;
        g_cursor[i] = pre;
        pre += g_hist[i];
        g_hist[i] = 0;
    }
    if (t == 1023) g_row[NN] = sm[1023];
}

// ---------------- launch 3: fused scatter+gather ----------------
__global__ void k_scatter_gather(const int* __restrict__ src, const int* __restrict__ dst,
                                 const int* __restrict__ e_tok) {
    int i = blockIdx.x * blockDim.x + threadIdx.x;
    if (i >= EE) return;
    int d = dst[i];
    int p = atomicAdd(&g_cursor[d], 1);
    g_srcS[p] = src[i];
    g_dstS[p] = d;
    g_etokS[p] = e_tok[i];
}

// ---------------- edge kernel: 32 edges/warp, tf32 3-term, truncation split --
// stores w = exp(logit) directly (exp moved out of agg)
__global__ void __launch_bounds__(256)
k_edge_mma(const float* __restrict__ Wf, const float* __restrict__ attn,
           const float* __restrict__ e_emb, int flags) {
    extern __shared__ float4 dsm[];
    float4* bfragP = dsm;                    // ks*128 + nf*32 + lane
    float*  As     = (float*)(dsm + 512);
    float*  etab   = As + 32;                // VOCAB*33 (layer 0 only)
    const int swap = flags & 1, first = flags & 2, lastl = flags & 4;
    int tid = threadIdx.x;
#pragma unroll
    for (int e2 = 0; e2 < 2; e2++) {
        int eid = tid + e2 * 256;
        int ks = eid >> 7, nf = (eid >> 5) & 3, ln = eid & 31;
        // k-permuted rows: slot (ln&3) <- col ks*8 + 2*(ln&3); slot +4 <- col +1
        int k0 = ks * 8 + 2 * (ln & 3);
        int n  = nf * 8 + (ln >> 2);
        float b0 = Wf[k0 * 32 + n];
        float b1 = Wf[(k0 + 1) * 32 + n];
        unsigned b0b = f2tf32(b0);
        unsigned b0s = f2tf32(b0 - __uint_as_float(b0b));
        unsigned b1b = f2tf32(b1);
        unsigned b1s = f2tf32(b1 - __uint_as_float(b1b));
        bfragP[ks * 128 + nf * 32 + ln] =
            make_float4(__uint_as_float(b0b), __uint_as_float(b0s),
                        __uint_as_float(b1b), __uint_as_float(b1s));
    }
    if (tid < 32) As[tid] = attn[tid];
    if (first) {
        for (int i = tid; i < VOCAB * DD; i += 256)
            etab[(i >> 5) * 33 + (i & 31)] = e_emb[i];
    }
    __syncthreads();

    int warp = tid >> 5;
    int lane = tid & 31;
    int base = (blockIdx.x * 8 + warp) * 32;   // 32 edges per warp
    if (base >= EE) return;
    unsigned off0 = (unsigned)(base >> 4) * 128u;   // float4 index of tile0

    const float4* ein4 = (const float4*)(swap ? g_f : g_e);
    float4*       fout4 = (float4*)(swap ? g_e : g_f);

    int r0 = lane >> 2;
    int t = lane & 3;
    int eA0 = base + r0,      eA1 = eA0 + 8;
    int eB0 = base + 16 + r0, eB1 = eB0 + 8;

    int tA0 = 0, tA1 = 0, tB0 = 0, tB1 = 0;
    if (first) {
        tA0 = g_etokS[eA0] * 33; tA1 = g_etokS[eA1] * 33;
        tB0 = g_etokS[eB0] * 33; tB1 = g_etokS[eB1] * 33;
    }

    float acc[8][4];
#pragma unroll
    for (int nf = 0; nf < 8; nf++)
#pragma unroll
        for (int q = 0; q < 4; q++) acc[nf][q] = 0.f;

#pragma unroll
    for (int ks = 0; ks < 4; ks++) {
        float4 va, vb;   // C-frag order {(r0,2t),(r0,2t+1),(r1,2t),(r1,2t+1)}
        if (first) {
            int c = ks * 8 + 2 * t;
            va.x = etab[tA0 + c]; va.y = etab[tA0 + c + 1];
            va.z = etab[tA1 + c]; va.w = etab[tA1 + c + 1];
            vb.x = etab[tB0 + c]; vb.y = etab[tB0 + c + 1];
            vb.z = etab[tB1 + c]; vb.w = etab[tB1 + c + 1];
        } else {
            va = ein4[off0 + ks * 32 + lane];
            vb = ein4[off0 + 128 + ks * 32 + lane];
        }
        unsigned ab0, as0, ab1, as1, ab2, as2, ab3, as3;
        SPLITT(va.x, ab0, as0); SPLITT(va.z, ab1, as1);
        SPLITT(va.y, ab2, as2); SPLITT(va.w, ab3, as3);
        unsigned cb0, cs0, cb1, cs1, cb2, cs2, cb3, cs3;
        SPLITT(vb.x, cb0, cs0); SPLITT(vb.z, cb1, cs1);
        SPLITT(vb.y, cb2, cs2); SPLITT(vb.w, cb3, cs3);
#pragma unroll
        for (int nf = 0; nf < 4; nf++) {
            float4 bv = bfragP[ks * 128 + nf * 32 + lane];
            unsigned b0b = __float_as_uint(bv.x), b0s = __float_as_uint(bv.y);
            unsigned b1b = __float_as_uint(bv.z), b1s = __float_as_uint(bv.w);
            MMA_TF32(acc[nf],     ab0, ab1, ab2, ab3, b0b, b1b);
            MMA_TF32(acc[4 + nf], cb0, cb1, cb2, cb3, b0b, b1b);
            MMA_TF32(acc[nf],     ab0, ab1, ab2, ab3, b0s, b1s);
            MMA_TF32(acc[4 + nf], cb0, cb1, cb2, cb3, b0s, b1s);
            MMA_TF32(acc[nf],     as0, as1, as2, as3, b0b, b1b);
            MMA_TF32(acc[4 + nf], cs0, cs1, cs2, cs3, b0b, b1b);
        }
    }

    // epilogue indices loaded AFTER the MMA loop (shorter live range)
    int sA0 = g_srcS[eA0], sA1 = g_srcS[eA1], sB0 = g_srcS[eB0], sB1 = g_srcS[eB1];
    int dA0 = g_dstS[eA0], dA1 = g_dstS[eA1], dB0 = g_dstS[eB0], dB1 = g_dstS[eB1];

    const float2* hi2 = (const float2*)g_hi;
    const float2* hj2 = (const float2*)g_hj;

#pragma unroll
    for (int tl = 0; tl < 2; tl++) {
        int s0 = tl ? sB0 : sA0, s1 = tl ? sB1 : sA1;
        int d0 = tl ? dB0 : dA0, d1 = tl ? dB1 : dA1;
        int e0 = tl ? eB0 : eA0, e1 = tl ? eB1 : eA1;
        float2 hia[4], hja[4], hib[4], hjb[4];
#pragma unroll
        for (int nf = 0; nf < 4; nf++) {
            hia[nf] = hi2[s0 * 16 + nf * 4 + t];
            hja[nf] = hj2[d0 * 16 + nf * 4 + t];
            hib[nf] = hi2[s1 * 16 + nf * 4 + t];
            hjb[nf] = hj2[d1 * 16 + nf * 4 + t];
        }
        float p0 = 0.f, p1 = 0.f;
#pragma unroll
        for (int nf = 0; nf < 4; nf++) {
            int n0 = nf * 8 + t * 2;
            float* a4 = acc[tl * 4 + nf];
            float v0 = a4[0] + hia[nf].x + hja[nf].x;
            float v1 = a4[1] + hia[nf].y + hja[nf].y;
            float v2 = a4[2] + hib[nf].x + hjb[nf].x;
            float v3 = a4[3] + hib[nf].y + hjb[nf].y;
            v0 = (v0 > 0.f) ? v0 : 0.01f * v0;
            v1 = (v1 > 0.f) ? v1 : 0.01f * v1;
            v2 = (v2 > 0.f) ? v2 : 0.01f * v2;
            v3 = (v3 > 0.f) ? v3 : 0.01f * v3;
            float a0 = As[n0], a1 = As[n0 + 1];
            p0 += v0 * a0 + v1 * a1;
            p1 += v2 * a0 + v3 * a1;
            if (!lastl)
                fout4[off0 + tl * 128 + nf * 32 + lane] = make_float4(v0, v1, v2, v3);
        }
        p0 += __shfl_xor_sync(0xffffffffu, p0, 1);
        p0 += __shfl_xor_sync(0xffffffffu, p0, 2);
        p1 += __shfl_xor_sync(0xffffffffu, p1, 1);
        p1 += __shfl_xor_sync(0xffffffffu, p1, 2);
        if (t == 0) {
            g_w[e0] = __expf(p0);
            g_w[e1] = __expf(p1);
        }
    }
}

// ---------------- agg (+relu) fused with next layer's projections ----------
// reads precomputed weights; exact trip bound; dual accumulators; float4 proj
__global__ void k_aggproj(const float* __restrict__ Wni, const float* __restrict__ Wnj,
                          const float* __restrict__ Wn, const float* __restrict__ b,
                          int last) {
    __shared__ float wT[3][32][36];
    __shared__ float bs[32];
    int tid = threadIdx.x;
    if (!last) stage_wT(Wni, Wnj, Wn, b, wT, bs, tid);
    __syncthreads();
    int node = blockIdx.x * 8 + (tid >> 5);
    int lane = tid & 31;
    if (node >= NN) return;
    int beg = g_row[node], end = g_row[node + 1];
    int deg = end - beg;
    int full_end = beg + (deg & ~31);
    float s = 0.f, acc0 = 0.f, acc1 = 0.f;
    // full 32-edge chunks
    for (int chunk = beg; chunk < full_end; chunk += 32) {
        float w = g_w[chunk + lane];
        int sv = g_srcS[chunk + lane];
        s += w;
#pragma unroll
        for (int e = 0; e < 32; e += 2) {
            float we0 = __shfl_sync(0xffffffffu, w, e);
            int   se0 = __shfl_sync(0xffffffffu, sv, e);
            float we1 = __shfl_sync(0xffffffffu, w, e + 1);
            int   se1 = __shfl_sync(0xffffffffu, sv, e + 1);
            acc0 += we0 * g_hn[se0 * DD + lane];
            acc1 += we1 * g_hn[se1 * DD + lane];
        }
    }
    // tail: exact trip count
    int lim = end - full_end;
    if (lim > 0) {
        int i = full_end + lane;
        float w = 0.f;
        int sv = 0;
        if (lane < lim) {
            w = g_w[i];
            sv = g_srcS[i];
        }
        s += w;
        for (int e = 0; e < lim; e++) {
            float we = __shfl_sync(0xffffffffu, w, e);
            int se = __shfl_sync(0xffffffffu, sv, e);
            acc0 += we * g_hn[se * DD + lane];
        }
    }
#pragma unroll
    for (int o = 16; o; o >>= 1) s += __shfl_xor_sync(0xffffffffu, s, o);
    float hv = (deg > 0) ? fmaxf((acc0 + acc1) / s, 0.f) : 0.f;

    if (last) {
        g_h[node * DD + lane] = hv;
        float v = hv;
#pragma unroll
        for (int o = 16; o; o >>= 1) v = fmaxf(v, __shfl_xor_sync(0xffffffffu, v, o));
        if (lane == 0) g_rowmax[node] = v;
    } else {
        float ai, aj, an;
        proj3(hv, lane, wT, bs, ai, aj, an);
        g_hi[node * DD + lane] = ai;
        g_hj[node * DD + lane] = aj;
        g_hn[node * DD + lane] = an;
    }
}

// ---------------- SortPooling + MLP head ----------------
// single-pass local top-8 -> warp merge -> final merge (tie: value desc, index asc)
__global__ void k_head(const float* __restrict__ Wlin, const float* __restrict__ blin,
                       const float* __restrict__ W1, const float* __restrict__ b1,
                       const float* __restrict__ W2, const float* __restrict__ b2,
                       const float* __restrict__ Wc, const float* __restrict__ bc,
                       float* __restrict__ out) {
    __shared__ float wv[8][TOPK];
    __shared__ int   wiids[8][TOPK];
    __shared__ int picked[TOPK];
    __shared__ float xs[TOPK * DD];
    __shared__ float y1[32], y2[32], y3[32];
    int tid = threadIdx.x;
    int wid = tid >> 5, lane = tid & 31;

    float lv[TOPK];
    int   li[TOPK];
#pragma unroll
    for (int k = 0; k < TOPK; k++) { lv[k] = -1e30f; li[k] = 0x7fffffff; }
    for (int i = tid; i < NN; i += 256) {
        float v = g_rowmax[i];
        if (v > lv[TOPK - 1] || (v == lv[TOPK - 1] && i < li[TOPK - 1])) {
            int k = TOPK - 1;
            while (k > 0 && (v > lv[k - 1] || (v == lv[k - 1] && i < li[k - 1]))) {
                lv[k] = lv[k - 1]; li[k] = li[k - 1]; k--;
            }
            lv[k] = v; li[k] = i;
        }
    }
    {
        float mv[TOPK];
        int   mi[TOPK];
#pragma unroll
        for (int k = 0; k < TOPK; k++) { mv[k] = lv[k]; mi[k] = li[k]; }
#pragma unroll
        for (int o = 16; o; o >>= 1) {
            float ov[TOPK];
            int   oi[TOPK];
#pragma unroll
            for (int k = 0; k < TOPK; k++) {
                ov[k] = __shfl_xor_sync(0xffffffffu, mv[k], o);
                oi[k] = __shfl_xor_sync(0xffffffffu, mi[k], o);
            }
            float rv[TOPK];
            int   ri[TOPK];
            int a = 0, c = 0;
#pragma unroll
            for (int k = 0; k < TOPK; k++) {
                bool takeA = (c >= TOPK) ||
                             (a < TOPK && (mv[a] > ov[c] || (mv[a] == ov[c] && mi[a] < oi[c])));
                if (takeA) { rv[k] = mv[a]; ri[k] = mi[a]; a++; }
                else       { rv[k] = ov[c]; ri[k] = oi[c]; c++; }
            }
#pragma unroll
            for (int k = 0; k < TOPK; k++) { mv[k] = rv[k]; mi[k] = ri[k]; }
        }
        if (lane == 0) {
#pragma unroll
            for (int k = 0; k < TOPK; k++) { wv[wid][k] = mv[k]; wiids[wid][k] = mi[k]; }
        }
    }
    __syncthreads();
    if (tid == 0) {
        float fv[TOPK];
        int   fi[TOPK];
#pragma unroll
        for (int k = 0; k < TOPK; k++) { fv[k] = -1e30f; fi[k] = 0x7fffffff; }
        for (int w = 0; w < 8; w++) {
            for (int k = 0; k < TOPK; k++) {
                float v = wv[w][k];
                int   i = wiids[w][k];
                if (v > fv[TOPK - 1] || (v == fv[TOPK - 1] && i < fi[TOPK - 1])) {
                    int k2 = TOPK - 1;
                    while (k2 > 0 && (v > fv[k2 - 1] || (v == fv[k2 - 1] && i < fi[k2 - 1]))) {
                        fv[k2] = fv[k2 - 1]; fi[k2] = fi[k2 - 1]; k2--;
                    }
                    fv[k2] = v; fi[k2] = i;
                }
            }
        }
#pragma unroll
        for (int k = 0; k < TOPK; k++) picked[k] = fi[k];
    }
    __syncthreads();

    if (tid < TOPK) {
        float r[32];
        int n = picked[tid];
        for (int d = 0; d < 32; d++) r[d] = g_h[n * DD + d];
        for (int a = 1; a < 32; a++) {
            float key = r[a];
            int b2_ = a - 1;
            while (b2_ >= 0 && r[b2_] > key) { r[b2_ + 1] = r[b2_]; b2_--; }
            r[b2_ + 1] = key;
        }
        for (int d = 0; d < 32; d++) xs[tid * 32 + d] = r[d];
    }
    __syncthreads();

    if (tid < 32) {
        float a = blin[tid];
        for (int i = 0; i < 256; i++) a += xs[i] * Wlin[i * 32 + tid];
        y1[tid] = fmaxf(a, 0.f);
    }
    __syncthreads();
    if (tid < 32) {
        float a = b1[tid];
        for (int k = 0; k < 32; k++) a += y1[k] * W1[k * 32 + tid];
        y2[tid] = fmaxf(a, 0.f);
    }
    __syncthreads();
    if (tid < 32) {
        float a = b2[tid];
        for (int k = 0; k < 32; k++) a += y2[k] * W2[k * 32 + tid];
        y3[tid] = fmaxf(a, 0.f);
    }
    __syncthreads();
    if (tid < 2) {
        float a = bc[tid];
        for (int k = 0; k < 32; k++) a += y3[k] * Wc[k * 2 + tid];
        out[tid] = a;
    }
}

// ---------------- launch ----------------
extern "C" void kernel_launch(void* const* d_in, const int* in_sizes, int n_in,
                              void* d_out, int out_size) {
    (void)in_sizes; (void)n_in; (void)out_size;
    const int*   h_tok     = (const int*)d_in[0];
    const int*   e_tok     = (const int*)d_in[1];
    const int*   src       = (const int*)d_in[2];
    const int*   dst       = (const int*)d_in[3];
    const float* tok_emb   = (const float*)d_in[4];
    const float* e_tok_emb = (const float*)d_in[5];
    const float* W_ni      = (const float*)d_in[6];
    const float* W_nj      = (const float*)d_in[7];
    const float* W_fij     = (const float*)d_in[8];
    const float* b_edge    = (const float*)d_in[9];
    const float* attn      = (const float*)d_in[10];
    const float* W_node    = (const float*)d_in[11];
    const float* W_lin     = (const float*)d_in[12];
    const float* b_lin     = (const float*)d_in[13];
    const float* W1        = (const float*)d_in[14];
    const float* b1        = (const float*)d_in[15];
    const float* W2        = (const float*)d_in[16];
    const float* b2        = (const float*)d_in[17];
    const float* Wc        = (const float*)d_in[18];
    const float* bc        = (const float*)d_in[19];
    float* out = (float*)d_out;

    const int MB = (EE + 255) / 256;                      // 6250 (32 edges/warp)
    const size_t SM_BASE  = 512 * 16 + 32 * 4;            // 8320
    const size_t SM_FIRST = SM_BASE + VOCAB * 33 * 4;     // 21520

    k_hist_init<<<EB + WB, 256>>>(dst, h_tok, tok_emb, W_ni, W_nj, W_node, b_edge);
    k_scan<<<1, 1024>>>();
    k_scatter_gather<<<EB, 256>>>(src, dst, e_tok);

    for (int l = 0; l < NLAYERS; l++) {
        int flags = (l & 1) | ((l == 0) ? 2 : 0) | ((l == NLAYERS - 1) ? 4 : 0);
        k_edge_mma<<<MB, 256, (l == 0) ? SM_FIRST : SM_BASE>>>(
            W_fij + l * 1024, attn + l * 32, e_tok_emb, flags);
        if (l < NLAYERS - 1) {
            k_aggproj<<<WB, 256>>>(W_ni + (l + 1) * 1024, W_nj + (l + 1) * 1024,
                                   W_node + (l + 1) * 1024, b_edge + (l + 1) * 32, 0);
        } else {
            k_aggproj<<<WB, 256>>>(W_ni, W_nj, W_node, b_edge, 1);
        }
    }

    k_head<<<1, 256>>>(W_lin, b_lin, W1, b1, W2, b2, Wc, bc, out);
}

// round 15
// speedup vs baseline: 1.0341x; 1.0341x over previous
#include <cuda_runtime.h>
#include <cuda_bf16.h>

#define NN 50000
#define EE 1600000
#define DD 32
#define NLAYERS 8
#define TOPK 8
#define VOCAB 100

// ---------------- device scratch (static, no allocations) ----------------
__device__ float g_hi[NN*DD];
__device__ float g_hj[NN*DD];
__device__ float g_hn[NN*DD];
__device__ float g_h [NN*DD];
// e/f in MMA C-fragment order (f32) per 16-edge tile
__device__ float4 g_e[EE*8];
__device__ float4 g_f[EE*8];
__device__ float g_logits[EE];
__device__ int   g_srcS[EE];
__device__ int   g_dstS[EE];
__device__ int   g_etokS[EE];
__device__ int   g_hist[NN];       // static zero-init; re-zeroed by k_scan each call
__device__ int   g_row [NN+1];
__device__ int   g_cursor[NN];
__device__ float g_rowmax[NN];

__device__ __forceinline__ unsigned f2tf32(float x) {
    unsigned r;
    asm("cvt.rna.tf32.f32 %0, %1;" : "=r"(r) : "f"(x));
    return r;
}

// truncation split: BIG = low-13-bits-masked (exact tf32), SMALL = exact residual
#define SPLITT(F, B, S) do {                                         \
    unsigned _b = __float_as_uint(F) & 0xffffe000u;                  \
    (B) = _b;                                                        \
    (S) = __float_as_uint((F) - __uint_as_float(_b));                \
} while (0)

#define MMA_TF32(ACC, A0, A1, A2, A3, B0, B1)                                   \
    asm volatile("mma.sync.aligned.m16n8k8.row.col.f32.tf32.tf32.f32 "          \
                 "{%0,%1,%2,%3}, {%4,%5,%6,%7}, {%8,%9}, {%0,%1,%2,%3};"        \
                 : "+f"(ACC[0]), "+f"(ACC[1]), "+f"(ACC[2]), "+f"(ACC[3])       \
                 : "r"(A0), "r"(A1), "r"(A2), "r"(A3), "r"(B0), "r"(B1))

#define EB 6250   // edge blocks (256 thr)
#define WB 6250   // node warp-blocks for init (8 nodes per 256-thr block)
#define AB 3125   // aggproj blocks (16 nodes per 512-thr block)

// ---------------- launch 1: hist (blocks 0..EB-1) + init_proj ----------------
__global__ void k_hist_init(const int* __restrict__ dst,
                            const int* __restrict__ h_tok, const float* __restrict__ tok_emb,
                            const float* __restrict__ Wni, const float* __restrict__ Wnj,
                            const float* __restrict__ Wn, const float* __restrict__ b) {
    if (blockIdx.x < EB) {
        int i = blockIdx.x * 256 + threadIdx.x;
        if (i < EE) atomicAdd(&g_hist[dst[i]], 1);
        return;
    }
    __shared__ float wi[32][32], wj[32][32], wn[32][32], bs[32];
    int tid = threadIdx.x;
    for (int i = tid; i < 1024; i += 256) {
        wi[i >> 5][i & 31] = Wni[i];
        wj[i >> 5][i & 31] = Wnj[i];
        wn[i >> 5][i & 31] = Wn[i];
    }
    if (tid < 32) bs[tid] = b[tid];
    __syncthreads();
    int node = (blockIdx.x - EB) * 8 + (tid >> 5);
    int lane = tid & 31;
    if (node >= NN) return;
    float hv = fmaxf(tok_emb[h_tok[node] * DD + lane], 0.f);
    float ai = bs[lane], aj = 0.f, an = 0.f;
#pragma unroll
    for (int k = 0; k < 32; k++) {
        float hk = __shfl_sync(0xffffffffu, hv, k);
        ai += hk * wi[k][lane];
        aj += hk * wj[k][lane];
        an += hk * wn[k][lane];
    }
    g_hi[node * DD + lane] = ai;
    g_hj[node * DD + lane] = aj;
    g_hn[node * DD + lane] = an;
}

// ---------------- launch 2: scan ----------------
__global__ void k_scan() {
    __shared__ int sm[1024];
    int t = threadIdx.x;
    const int CH = (NN + 1023) / 1024;
    int b0 = t * CH;
    int b1 = min(b0 + CH, NN);
    int sum = 0;
    for (int i = b0; i < b1; i++) sum += g_hist[i];
    sm[t] = sum;
    __syncthreads();
    for (int off = 1; off < 1024; off <<= 1) {
        int v = (t >= off) ? sm[t - off] : 0;
        __syncthreads();
        sm[t] += v;
        __syncthreads();
    }
    int pre = sm[t] - sum;
    for (int i = b0; i < b1; i++) {
        g_row[i] = pre;
        g_cursor[i] = pre;
        pre += g_hist[i];
        g_hist[i] = 0;
    }
    if (t == 1023) g_row[NN] = sm[1023];
}

// ---------------- launch 3: fused scatter+gather ----------------
__global__ void k_scatter_gather(const int* __restrict__ src, const int* __restrict__ dst,
                                 const int* __restrict__ e_tok) {
    int i = blockIdx.x * blockDim.x + threadIdx.x;
    if (i >= EE) return;
    int d = dst[i];
    int p = atomicAdd(&g_cursor[d], 1);
    g_srcS[p] = src[i];
    g_dstS[p] = d;
    g_etokS[p] = e_tok[i];
}

// ---------------- edge kernel: 32 edges/warp, tf32 3-term, truncation split --
// (R12/R13 proven-best edge config, unchanged)
__global__ void __launch_bounds__(256)
k_edge_mma(const float* __restrict__ Wf, const float* __restrict__ attn,
           const float* __restrict__ e_emb, int flags) {
    extern __shared__ float4 dsm[];
    float4* bfragP = dsm;                    // ks*128 + nf*32 + lane
    float*  As     = (float*)(dsm + 512);
    float*  etab   = As + 32;                // VOCAB*33 (layer 0 only)
    const int swap = flags & 1, first = flags & 2, lastl = flags & 4;
    int tid = threadIdx.x;
#pragma unroll
    for (int e2 = 0; e2 < 2; e2++) {
        int eid = tid + e2 * 256;
        int ks = eid >> 7, nf = (eid >> 5) & 3, ln = eid & 31;
        // k-permuted rows: slot (ln&3) <- col ks*8 + 2*(ln&3); slot +4 <- col +1
        int k0 = ks * 8 + 2 * (ln & 3);
        int n  = nf * 8 + (ln >> 2);
        float b0 = Wf[k0 * 32 + n];
        float b1 = Wf[(k0 + 1) * 32 + n];
        unsigned b0b = f2tf32(b0);
        unsigned b0s = f2tf32(b0 - __uint_as_float(b0b));
        unsigned b1b = f2tf32(b1);
        unsigned b1s = f2tf32(b1 - __uint_as_float(b1b));
        bfragP[ks * 128 + nf * 32 + ln] =
            make_float4(__uint_as_float(b0b), __uint_as_float(b0s),
                        __uint_as_float(b1b), __uint_as_float(b1s));
    }
    if (tid < 32) As[tid] = attn[tid];
    if (first) {
        for (int i = tid; i < VOCAB * DD; i += 256)
            etab[(i >> 5) * 33 + (i & 31)] = e_emb[i];
    }
    __syncthreads();

    int warp = tid >> 5;
    int lane = tid & 31;
    int base = (blockIdx.x * 8 + warp) * 32;   // 32 edges per warp
    if (base >= EE) return;
    unsigned off0 = (unsigned)(base >> 4) * 128u;   // float4 index of tile0

    const float4* ein4 = (const float4*)(swap ? g_f : g_e);
    float4*       fout4 = (float4*)(swap ? g_e : g_f);

    int r0 = lane >> 2;
    int t = lane & 3;
    int eA0 = base + r0,      eA1 = eA0 + 8;
    int eB0 = base + 16 + r0, eB1 = eB0 + 8;

    int tA0 = 0, tA1 = 0, tB0 = 0, tB1 = 0;
    if (first) {
        tA0 = g_etokS[eA0] * 33; tA1 = g_etokS[eA1] * 33;
        tB0 = g_etokS[eB0] * 33; tB1 = g_etokS[eB1] * 33;
    }

    float acc[8][4];
#pragma unroll
    for (int nf = 0; nf < 8; nf++)
#pragma unroll
        for (int q = 0; q < 4; q++) acc[nf][q] = 0.f;

#pragma unroll
    for (int ks = 0; ks < 4; ks++) {
        float4 va, vb;   // C-frag order {(r0,2t),(r0,2t+1),(r1,2t),(r1,2t+1)}
        if (first) {
            int c = ks * 8 + 2 * t;
            va.x = etab[tA0 + c]; va.y = etab[tA0 + c + 1];
            va.z = etab[tA1 + c]; va.w = etab[tA1 + c + 1];
            vb.x = etab[tB0 + c]; vb.y = etab[tB0 + c + 1];
            vb.z = etab[tB1 + c]; vb.w = etab[tB1 + c + 1];
        } else {
            va = ein4[off0 + ks * 32 + lane];
            vb = ein4[off0 + 128 + ks * 32 + lane];
        }
        unsigned ab0, as0, ab1, as1, ab2, as2, ab3, as3;
        SPLITT(va.x, ab0, as0); SPLITT(va.z, ab1, as1);
        SPLITT(va.y, ab2, as2); SPLITT(va.w, ab3, as3);
        unsigned cb0, cs0, cb1, cs1, cb2, cs2, cb3, cs3;
        SPLITT(vb.x, cb0, cs0); SPLITT(vb.z, cb1, cs1);
        SPLITT(vb.y, cb2, cs2); SPLITT(vb.w, cb3, cs3);
#pragma unroll
        for (int nf = 0; nf < 4; nf++) {
            float4 bv = bfragP[ks * 128 + nf * 32 + lane];
            unsigned b0b = __float_as_uint(bv.x), b0s = __float_as_uint(bv.y);
            unsigned b1b = __float_as_uint(bv.z), b1s = __float_as_uint(bv.w);
            MMA_TF32(acc[nf],     ab0, ab1, ab2, ab3, b0b, b1b);
            MMA_TF32(acc[4 + nf], cb0, cb1, cb2, cb3, b0b, b1b);
            MMA_TF32(acc[nf],     ab0, ab1, ab2, ab3, b0s, b1s);
            MMA_TF32(acc[4 + nf], cb0, cb1, cb2, cb3, b0s, b1s);
            MMA_TF32(acc[nf],     as0, as1, as2, as3, b0b, b1b);
            MMA_TF32(acc[4 + nf], cs0, cs1, cs2, cs3, b0b, b1b);
        }
    }

    // epilogue indices loaded AFTER the MMA loop (shorter live range)
    int sA0 = g_srcS[eA0], sA1 = g_srcS[eA1], sB0 = g_srcS[eB0], sB1 = g_srcS[eB1];
    int dA0 = g_dstS[eA0], dA1 = g_dstS[eA1], dB0 = g_dstS[eB0], dB1 = g_dstS[eB1];

    const float2* hi2 = (const float2*)g_hi;
    const float2* hj2 = (const float2*)g_hj;

#pragma unroll
    for (int tl = 0; tl < 2; tl++) {
        int s0 = tl ? sB0 : sA0, s1 = tl ? sB1 : sA1;
        int d0 = tl ? dB0 : dA0, d1 = tl ? dB1 : dA1;
        int e0 = tl ? eB0 : eA0, e1 = tl ? eB1 : eA1;
        float2 hia[4], hja[4], hib[4], hjb[4];
#pragma unroll
        for (int nf = 0; nf < 4; nf++) {
            hia[nf] = hi2[s0 * 16 + nf * 4 + t];
            hja[nf] = hj2[d0 * 16 + nf * 4 + t];
            hib[nf] = hi2[s1 * 16 + nf * 4 + t];
            hjb[nf] = hj2[d1 * 16 + nf * 4 + t];
        }
        float p0 = 0.f, p1 = 0.f;
#pragma unroll
        for (int nf = 0; nf < 4; nf++) {
            int n0 = nf * 8 + t * 2;
            float* a4 = acc[tl * 4 + nf];
            float v0 = a4[0] + hia[nf].x + hja[nf].x;
            float v1 = a4[1] + hia[nf].y + hja[nf].y;
            float v2 = a4[2] + hib[nf].x + hjb[nf].x;
            float v3 = a4[3] + hib[nf].y + hjb[nf].y;
            v0 = (v0 > 0.f) ? v0 : 0.01f * v0;
            v1 = (v1 > 0.f) ? v1 : 0.01f * v1;
            v2 = (v2 > 0.f) ? v2 : 0.01f * v2;
            v3 = (v3 > 0.f) ? v3 : 0.01f * v3;
            float a0 = As[n0], a1 = As[n0 + 1];
            p0 += v0 * a0 + v1 * a1;
            p1 += v2 * a0 + v3 * a1;
            if (!lastl)
                fout4[off0 + tl * 128 + nf * 32 + lane] = make_float4(v0, v1, v2, v3);
        }
        p0 += __shfl_xor_sync(0xffffffffu, p0, 1);
        p0 += __shfl_xor_sync(0xffffffffu, p0, 2);
        p1 += __shfl_xor_sync(0xffffffffu, p1, 1);
        p1 += __shfl_xor_sync(0xffffffffu, p1, 2);
        if (t == 0) {
            g_logits[e0] = p0;
            g_logits[e1] = p1;
        }
    }
}

// ---------------- agg (+relu) fused with next layer's projections ----------
// R13 structure; 512-thr blocks (16 nodes) to halve weight-restaging + prologues;
// dual accumulators in the gather loop.
__global__ void k_aggproj(const float* __restrict__ Wni, const float* __restrict__ Wnj,
                          const float* __restrict__ Wn, const float* __restrict__ b,
                          int last) {
    __shared__ float wi[32][32], wj[32][32], wn[32][32], bs[32];
    int tid = threadIdx.x;
    if (!last) {
        for (int i = tid; i < 1024; i += 512) {
            wi[i >> 5][i & 31] = Wni[i];
            wj[i >> 5][i & 31] = Wnj[i];
            wn[i >> 5][i & 31] = Wn[i];
        }
        if (tid < 32) bs[tid] = b[tid];
    }
    __syncthreads();
    int node = blockIdx.x * 16 + (tid >> 5);
    int lane = tid & 31;
    if (node >= NN) return;
    int beg = g_row[node], end = g_row[node + 1];
    int deg = end - beg;
    int full_end = beg + (deg & ~31);
    float s = 0.f, acc0 = 0.f, acc1 = 0.f;
    // full 32-edge chunks: unrolled, no bounds checks
    for (int chunk = beg; chunk < full_end; chunk += 32) {
        float w = __expf(g_logits[chunk + lane]);
        int sv = g_srcS[chunk + lane];
        s += w;
#pragma unroll
        for (int e = 0; e < 32; e += 2) {
            float we0 = __shfl_sync(0xffffffffu, w, e);
            int   se0 = __shfl_sync(0xffffffffu, sv, e);
            float we1 = __shfl_sync(0xffffffffu, w, e + 1);
            int   se1 = __shfl_sync(0xffffffffu, sv, e + 1);
            acc0 += we0 * g_hn[se0 * DD + lane];
            acc1 += we1 * g_hn[se1 * DD + lane];
        }
    }
    // tail chunk: exact trip count (uniform across the warp)
    int lim = end - full_end;
    if (lim > 0) {
        int i = full_end + lane;
        float w = 0.f;
        int sv = 0;
        if (lane < lim) {
            w = __expf(g_logits[i]);
            sv = g_srcS[i];
        }
        s += w;
        for (int e = 0; e < lim; e++) {
            float we = __shfl_sync(0xffffffffu, w, e);
            int se = __shfl_sync(0xffffffffu, sv, e);
            acc0 += we * g_hn[se * DD + lane];
        }
    }
#pragma unroll
    for (int o = 16; o; o >>= 1) s += __shfl_xor_sync(0xffffffffu, s, o);
    float hv = (deg > 0) ? fmaxf((acc0 + acc1) / s, 0.f) : 0.f;

    if (last) {
        g_h[node * DD + lane] = hv;
        float v = hv;
#pragma unroll
        for (int o = 16; o; o >>= 1) v = fmaxf(v, __shfl_xor_sync(0xffffffffu, v, o));
        if (lane == 0) g_rowmax[node] = v;
    } else {
        float ai = bs[lane], aj = 0.f, an = 0.f;
#pragma unroll
        for (int k = 0; k < 32; k++) {
            float hk = __shfl_sync(0xffffffffu, hv, k);
            ai += hk * wi[k][lane];
            aj += hk * wj[k][lane];
            an += hk * wn[k][lane];
        }
        g_hi[node * DD + lane] = ai;
        g_hj[node * DD + lane] = aj;
        g_hn[node * DD + lane] = an;
    }
}

// ---------------- SortPooling + MLP head ----------------
// single-pass local top-8 -> warp merge -> final merge (tie: value desc, index asc)
__global__ void k_head(const float* __restrict__ Wlin, const float* __restrict__ blin,
                       const float* __restrict__ W1, const float* __restrict__ b1,
                       const float* __restrict__ W2, const float* __restrict__ b2,
                       const float* __restrict__ Wc, const float* __restrict__ bc,
                       float* __restrict__ out) {
    __shared__ float wv[8][TOPK];
    __shared__ int   wiids[8][TOPK];
    __shared__ int picked[TOPK];
    __shared__ float xs[TOPK * DD];
    __shared__ float y1[32], y2[32], y3[32];
    int tid = threadIdx.x;
    int wid = tid >> 5, lane = tid & 31;

    float lv[TOPK];
    int   li[TOPK];
#pragma unroll
    for (int k = 0; k < TOPK; k++) { lv[k] = -1e30f; li[k] = 0x7fffffff; }
    for (int i = tid; i < NN; i += 256) {
        float v = g_rowmax[i];
        if (v > lv[TOPK - 1] || (v == lv[TOPK - 1] && i < li[TOPK - 1])) {
            int k = TOPK - 1;
            while (k > 0 && (v > lv[k - 1] || (v == lv[k - 1] && i < li[k - 1]))) {
                lv[k] = lv[k - 1]; li[k] = li[k - 1]; k--;
            }
            lv[k] = v; li[k] = i;
        }
    }
    {
        float mv[TOPK];
        int   mi[TOPK];
#pragma unroll
        for (int k = 0; k < TOPK; k++) { mv[k] = lv[k]; mi[k] = li[k]; }
#pragma unroll
        for (int o = 16; o; o >>= 1) {
            float ov[TOPK];
            int   oi[TOPK];
#pragma unroll
            for (int k = 0; k < TOPK; k++) {
                ov[k] = __shfl_xor_sync(0xffffffffu, mv[k], o);
                oi[k] = __shfl_xor_sync(0xffffffffu, mi[k], o);
            }
            float rv[TOPK];
            int   ri[TOPK];
            int a = 0, c = 0;
#pragma unroll
            for (int k = 0; k < TOPK; k++) {
                bool takeA = (c >= TOPK) ||
                             (a < TOPK && (mv[a] > ov[c] || (mv[a] == ov[c] && mi[a] < oi[c])));
                if (takeA) { rv[k] = mv[a]; ri[k] = mi[a]; a++; }
                else       { rv[k] = ov[c]; ri[k] = oi[c]; c++; }
            }
#pragma unroll
            for (int k = 0; k < TOPK; k++) { mv[k] = rv[k]; mi[k] = ri[k]; }
        }
        if (lane == 0) {
#pragma unroll
            for (int k = 0; k < TOPK; k++) { wv[wid][k] = mv[k]; wiids[wid][k] = mi[k]; }
        }
    }
    __syncthreads();
    if (tid == 0) {
        float fv[TOPK];
        int   fi[TOPK];
#pragma unroll
        for (int k = 0; k < TOPK; k++) { fv[k] = -1e30f; fi[k] = 0x7fffffff; }
        for (int w = 0; w < 8; w++) {
            for (int k = 0; k < TOPK; k++) {
                float v = wv[w][k];
                int   i = wiids[w][k];
                if (v > fv[TOPK - 1] || (v == fv[TOPK - 1] && i < fi[TOPK - 1])) {
                    int k2 = TOPK - 1;
                    while (k2 > 0 && (v > fv[k2 - 1] || (v == fv[k2 - 1] && i < fi[k2 - 1]))) {
                        fv[k2] = fv[k2 - 1]; fi[k2] = fi[k2 - 1]; k2--;
                    }
                    fv[k2] = v; fi[k2] = i;
                }
            }
        }
#pragma unroll
        for (int k = 0; k < TOPK; k++) picked[k] = fi[k];
    }
    __syncthreads();

    if (tid < TOPK) {
        float r[32];
        int n = picked[tid];
        for (int d = 0; d < 32; d++) r[d] = g_h[n * DD + d];
        for (int a = 1; a < 32; a++) {
            float key = r[a];
            int b2_ = a - 1;
            while (b2_ >= 0 && r[b2_] > key) { r[b2_ + 1] = r[b2_]; b2_--; }
            r[b2_ + 1] = key;
        }
        for (int d = 0; d < 32; d++) xs[tid * 32 + d] = r[d];
    }
    __syncthreads();

    if (tid < 32) {
        float a = blin[tid];
        for (int i = 0; i < 256; i++) a += xs[i] * Wlin[i * 32 + tid];
        y1[tid] = fmaxf(a, 0.f);
    }
    __syncthreads();
    if (tid < 32) {
        float a = b1[tid];
        for (int k = 0; k < 32; k++) a += y1[k] * W1[k * 32 + tid];
        y2[tid] = fmaxf(a, 0.f);
    }
    __syncthreads();
    if (tid < 32) {
        float a = b2[tid];
        for (int k = 0; k < 32; k++) a += y2[k] * W2[k * 32 + tid];
        y3[tid] = fmaxf(a, 0.f);
    }
    __syncthreads();
    if (tid < 2) {
        float a = bc[tid];
        for (int k = 0; k < 32; k++) a += y3[k] * Wc[k * 2 + tid];
        out[tid] = a;
    }
}

// ---------------- launch ----------------
extern "C" void kernel_launch(void* const* d_in, const int* in_sizes, int n_in,
                              void* d_out, int out_size) {
    (void)in_sizes; (void)n_in; (void)out_size;
    const int*   h_tok     = (const int*)d_in[0];
    const int*   e_tok     = (const int*)d_in[1];
    const int*   src       = (const int*)d_in[2];
    const int*   dst       = (const int*)d_in[3];
    const float* tok_emb   = (const float*)d_in[4];
    const float* e_tok_emb = (const float*)d_in[5];
    const float* W_ni      = (const float*)d_in[6];
    const float* W_nj      = (const float*)d_in[7];
    const float* W_fij     = (const float*)d_in[8];
    const float* b_edge    = (const float*)d_in[9];
    const float* attn      = (const float*)d_in[10];
    const float* W_node    = (const float*)d_in[11];
    const float* W_lin     = (const float*)d_in[12];
    const float* b_lin     = (const float*)d_in[13];
    const float* W1        = (const float*)d_in[14];
    const float* b1        = (const float*)d_in[15];
    const float* W2        = (const float*)d_in[16];
    const float* b2        = (const float*)d_in[17];
    const float* Wc        = (const float*)d_in[18];
    const float* bc        = (const float*)d_in[19];
    float* out = (float*)d_out;

    const int MB = (EE + 255) / 256;                      // 6250 (32 edges/warp)
    const size_t SM_BASE  = 512 * 16 + 32 * 4;            // 8320
    const size_t SM_FIRST = SM_BASE + VOCAB * 33 * 4;     // 21520

    k_hist_init<<<EB + WB, 256>>>(dst, h_tok, tok_emb, W_ni, W_nj, W_node, b_edge);
    k_scan<<<1, 1024>>>();
    k_scatter_gather<<<EB, 256>>>(src, dst, e_tok);

    for (int l = 0; l < NLAYERS; l++) {
        int flags = (l & 1) | ((l == 0) ? 2 : 0) | ((l == NLAYERS - 1) ? 4 : 0);
        k_edge_mma<<<MB, 256, (l == 0) ? SM_FIRST : SM_BASE>>>(
            W_fij + l * 1024, attn + l * 32, e_tok_emb, flags);
        if (l < NLAYERS - 1) {
            k_aggproj<<<AB, 512>>>(W_ni + (l + 1) * 1024, W_nj + (l + 1) * 1024,
                                   W_node + (l + 1) * 1024, b_edge + (l + 1) * 32, 0);
        } else {
            k_aggproj<<<AB, 512>>>(W_ni, W_nj, W_node, b_edge, 1);
        }
    }

    k_head<<<1, 256>>>(W_lin, b_lin, W1, b1, W2, b2, Wc, bc, out);
}

// round 16
// speedup vs baseline: 1.1238x; 1.0868x over previous
#include <cuda_runtime.h>
#include <cuda_bf16.h>

#define NN 50000
#define EE 1600000
#define DD 32
#define NLAYERS 8
#define TOPK 8
#define VOCAB 100

// ---------------- device scratch (static, no allocations) ----------------
__device__ float g_hi[NN*DD];
__device__ float g_hj[NN*DD];
__device__ float g_hn[NN*DD];
__device__ float g_h [NN*DD];
// e/f in MMA C-fragment order (f32) per 16-edge tile
__device__ float4 g_e[EE*8];
__device__ float4 g_f[EE*8];
__device__ float g_logits[EE];
__device__ int   g_srcS[EE];
__device__ int   g_dstS[EE];
__device__ int   g_etokS[EE];
__device__ int   g_hist[NN];       // static zero-init; re-zeroed by k_scan each call
__device__ int   g_row [NN+1];
__device__ int   g_cursor[NN];
__device__ float g_rowmax[NN];

__device__ __forceinline__ unsigned f2tf32(float x) {
    unsigned r;
    asm("cvt.rna.tf32.f32 %0, %1;" : "=r"(r) : "f"(x));
    return r;
}

// truncation split: BIG = low-13-bits-masked (exact tf32), SMALL = exact residual
#define SPLITT(F, B, S) do {                                         \
    unsigned _b = __float_as_uint(F) & 0xffffe000u;                  \
    (B) = _b;                                                        \
    (S) = __float_as_uint((F) - __uint_as_float(_b));                \
} while (0)

#define MMA_TF32(ACC, A0, A1, A2, A3, B0, B1)                                   \
    asm volatile("mma.sync.aligned.m16n8k8.row.col.f32.tf32.tf32.f32 "          \
                 "{%0,%1,%2,%3}, {%4,%5,%6,%7}, {%8,%9}, {%0,%1,%2,%3};"        \
                 : "+f"(ACC[0]), "+f"(ACC[1]), "+f"(ACC[2]), "+f"(ACC[3])       \
                 : "r"(A0), "r"(A1), "r"(A2), "r"(A3), "r"(B0), "r"(B1))

#define EB 6250   // edge blocks (256 thr)
#define WB 6250   // node warp-blocks for init (8 nodes per 256-thr block)
#define AB 3125   // aggproj blocks (16 nodes per 512-thr block)

// ---------------- launch 1: hist (blocks 0..EB-1) + init_proj ----------------
__global__ void k_hist_init(const int* __restrict__ dst,
                            const int* __restrict__ h_tok, const float* __restrict__ tok_emb,
                            const float* __restrict__ Wni, const float* __restrict__ Wnj,
                            const float* __restrict__ Wn, const float* __restrict__ b) {
    if (blockIdx.x < EB) {
        int i = blockIdx.x * 256 + threadIdx.x;
        if (i < EE) atomicAdd(&g_hist[dst[i]], 1);
        return;
    }
    __shared__ float wi[32][32], wj[32][32], wn[32][32], bs[32];
    int tid = threadIdx.x;
    for (int i = tid; i < 1024; i += 256) {
        wi[i >> 5][i & 31] = Wni[i];
        wj[i >> 5][i & 31] = Wnj[i];
        wn[i >> 5][i & 31] = Wn[i];
    }
    if (tid < 32) bs[tid] = b[tid];
    __syncthreads();
    int node = (blockIdx.x - EB) * 8 + (tid >> 5);
    int lane = tid & 31;
    if (node >= NN) return;
    float hv = fmaxf(tok_emb[h_tok[node] * DD + lane], 0.f);
    float ai = bs[lane], aj = 0.f, an = 0.f;
#pragma unroll
    for (int k = 0; k < 32; k++) {
        float hk = __shfl_sync(0xffffffffu, hv, k);
        ai += hk * wi[k][lane];
        aj += hk * wj[k][lane];
        an += hk * wn[k][lane];
    }
    g_hi[node * DD + lane] = ai;
    g_hj[node * DD + lane] = aj;
    g_hn[node * DD + lane] = an;
}

// ---------------- launch 2: scan ----------------
__global__ void k_scan() {
    __shared__ int sm[1024];
    int t = threadIdx.x;
    const int CH = (NN + 1023) / 1024;
    int b0 = t * CH;
    int b1 = min(b0 + CH, NN);
    int sum = 0;
    for (int i = b0; i < b1; i++) sum += g_hist[i];
    sm[t] = sum;
    __syncthreads();
    for (int off = 1; off < 1024; off <<= 1) {
        int v = (t >= off) ? sm[t - off] : 0;
        __syncthreads();
        sm[t] += v;
        __syncthreads();
    }
    int pre = sm[t] - sum;
    for (int i = b0; i < b1; i++) {
        g_row[i] = pre;
        g_cursor[i] = pre;
        pre += g_hist[i];
        g_hist[i] = 0;
    }
    if (t == 1023) g_row[NN] = sm[1023];
}

// ---------------- launch 3: fused scatter+gather ----------------
__global__ void k_scatter_gather(const int* __restrict__ src, const int* __restrict__ dst,
                                 const int* __restrict__ e_tok) {
    int i = blockIdx.x * blockDim.x + threadIdx.x;
    if (i >= EE) return;
    int d = dst[i];
    int p = atomicAdd(&g_cursor[d], 1);
    g_srcS[p] = src[i];
    g_dstS[p] = d;
    g_etokS[p] = e_tok[i];
}

// ---------------- edge kernel: 32 edges/warp, tf32 3-term, truncation split --
// e-tile input staged through shared memory via cp.async (zero register cost,
// latency hidden behind bfrag staging + syncthreads). MMA loop reads LDS only.
// flags: bit0 = swap, bit1 = first (e from token table), bit2 = last (skip f store)
// dyn smem: float4 bfrag[512] (8KB) | float As[32] | stage[8][256] float4 (32KB)
//           (layer0 aliases etab[VOCAB*33] over the stage region)
__global__ void __launch_bounds__(256)
k_edge_mma(const float* __restrict__ Wf, const float* __restrict__ attn,
           const float* __restrict__ e_emb, int flags) {
    extern __shared__ float4 dsm[];
    float4* bfragP = dsm;                    // ks*128 + nf*32 + lane
    float*  As     = (float*)(dsm + 512);
    float4* stageP = (float4*)(As + 32);     // [q*256 + tid], q = ks (va) / 4+ks (vb)
    float*  etab   = (float*)(As + 32);      // layer-0 alias
    const int swap = flags & 1, first = flags & 2, lastl = flags & 4;
    int tid = threadIdx.x;
    int warp = tid >> 5;
    int lane = tid & 31;
    int base = (blockIdx.x * 8 + warp) * 32;          // exact: grid*8*32 == EE
    unsigned off0 = (unsigned)(base >> 4) * 128u;     // float4 index of tile0

    const float4* ein4 = (const float4*)(swap ? g_f : g_e);
    float4*       fout4 = (float4*)(swap ? g_e : g_f);

    // issue async e-tile loads FIRST (latency hidden behind bfrag staging)
    if (!first) {
        unsigned sdst = (unsigned)__cvta_generic_to_shared(&stageP[tid]);
#pragma unroll
        for (int q = 0; q < 8; q++) {
            const float4* g = ein4 + off0 + (q & 3) * 32 + ((q & 4) ? 128 : 0) + lane;
            asm volatile("cp.async.cg.shared.global [%0], [%1], 16;"
                         :: "r"(sdst + q * 4096), "l"(g));
        }
        asm volatile("cp.async.commit_group;");
    }

#pragma unroll
    for (int e2 = 0; e2 < 2; e2++) {
        int eid = tid + e2 * 256;
        int ks = eid >> 7, nf = (eid >> 5) & 3, ln = eid & 31;
        // k-permuted rows: slot (ln&3) <- col ks*8 + 2*(ln&3); slot +4 <- col +1
        int k0 = ks * 8 + 2 * (ln & 3);
        int n  = nf * 8 + (ln >> 2);
        float b0 = Wf[k0 * 32 + n];
        float b1 = Wf[(k0 + 1) * 32 + n];
        unsigned b0b = f2tf32(b0);
        unsigned b0s = f2tf32(b0 - __uint_as_float(b0b));
        unsigned b1b = f2tf32(b1);
        unsigned b1s = f2tf32(b1 - __uint_as_float(b1b));
        bfragP[ks * 128 + nf * 32 + ln] =
            make_float4(__uint_as_float(b0b), __uint_as_float(b0s),
                        __uint_as_float(b1b), __uint_as_float(b1s));
    }
    if (tid < 32) As[tid] = attn[tid];
    if (first) {
        for (int i = tid; i < VOCAB * DD; i += 256)
            etab[(i >> 5) * 33 + (i & 31)] = e_emb[i];
    }
    __syncthreads();
    if (!first) asm volatile("cp.async.wait_group 0;");

    int r0 = lane >> 2;
    int t = lane & 3;
    int eA0 = base + r0,      eA1 = eA0 + 8;
    int eB0 = base + 16 + r0, eB1 = eB0 + 8;

    int tA0 = 0, tA1 = 0, tB0 = 0, tB1 = 0;
    if (first) {
        tA0 = g_etokS[eA0] * 33; tA1 = g_etokS[eA1] * 33;
        tB0 = g_etokS[eB0] * 33; tB1 = g_etokS[eB1] * 33;
    }

    float acc[8][4];
#pragma unroll
    for (int nf = 0; nf < 8; nf++)
#pragma unroll
        for (int q = 0; q < 4; q++) acc[nf][q] = 0.f;

#pragma unroll
    for (int ks = 0; ks < 4; ks++) {
        float4 va, vb;   // C-frag order {(r0,2t),(r0,2t+1),(r1,2t),(r1,2t+1)}
        if (first) {
            int c = ks * 8 + 2 * t;
            va.x = etab[tA0 + c]; va.y = etab[tA0 + c + 1];
            va.z = etab[tA1 + c]; va.w = etab[tA1 + c + 1];
            vb.x = etab[tB0 + c]; vb.y = etab[tB0 + c + 1];
            vb.z = etab[tB1 + c]; vb.w = etab[tB1 + c + 1];
        } else {
            va = stageP[ks * 256 + tid];
            vb = stageP[(4 + ks) * 256 + tid];
        }
        unsigned ab0, as0, ab1, as1, ab2, as2, ab3, as3;
        SPLITT(va.x, ab0, as0); SPLITT(va.z, ab1, as1);
        SPLITT(va.y, ab2, as2); SPLITT(va.w, ab3, as3);
        unsigned cb0, cs0, cb1, cs1, cb2, cs2, cb3, cs3;
        SPLITT(vb.x, cb0, cs0); SPLITT(vb.z, cb1, cs1);
        SPLITT(vb.y, cb2, cs2); SPLITT(vb.w, cb3, cs3);
#pragma unroll
        for (int nf = 0; nf < 4; nf++) {
            float4 bv = bfragP[ks * 128 + nf * 32 + lane];
            unsigned b0b = __float_as_uint(bv.x), b0s = __float_as_uint(bv.y);
            unsigned b1b = __float_as_uint(bv.z), b1s = __float_as_uint(bv.w);
            MMA_TF32(acc[nf],     ab0, ab1, ab2, ab3, b0b, b1b);
            MMA_TF32(acc[4 + nf], cb0, cb1, cb2, cb3, b0b, b1b);
            MMA_TF32(acc[nf],     ab0, ab1, ab2, ab3, b0s, b1s);
            MMA_TF32(acc[4 + nf], cb0, cb1, cb2, cb3, b0s, b1s);
            MMA_TF32(acc[nf],     as0, as1, as2, as3, b0b, b1b);
            MMA_TF32(acc[4 + nf], cs0, cs1, cs2, cs3, b0b, b1b);
        }
    }

    // epilogue indices loaded AFTER the MMA loop (shorter live range)
    int sA0 = g_srcS[eA0], sA1 = g_srcS[eA1], sB0 = g_srcS[eB0], sB1 = g_srcS[eB1];
    int dA0 = g_dstS[eA0], dA1 = g_dstS[eA1], dB0 = g_dstS[eB0], dB1 = g_dstS[eB1];

    const float2* hi2 = (const float2*)g_hi;
    const float2* hj2 = (const float2*)g_hj;

#pragma unroll
    for (int tl = 0; tl < 2; tl++) {
        int s0 = tl ? sB0 : sA0, s1 = tl ? sB1 : sA1;
        int d0 = tl ? dB0 : dA0, d1 = tl ? dB1 : dA1;
        int e0 = tl ? eB0 : eA0, e1 = tl ? eB1 : eA1;
        float2 hia[4], hja[4], hib[4], hjb[4];
#pragma unroll
        for (int nf = 0; nf < 4; nf++) {
            hia[nf] = hi2[s0 * 16 + nf * 4 + t];
            hja[nf] = hj2[d0 * 16 + nf * 4 + t];
            hib[nf] = hi2[s1 * 16 + nf * 4 + t];
            hjb[nf] = hj2[d1 * 16 + nf * 4 + t];
        }
        float p0 = 0.f, p1 = 0.f;
#pragma unroll
        for (int nf = 0; nf < 4; nf++) {
            int n0 = nf * 8 + t * 2;
            float* a4 = acc[tl * 4 + nf];
            float v0 = a4[0] + hia[nf].x + hja[nf].x;
            float v1 = a4[1] + hia[nf].y + hja[nf].y;
            float v2 = a4[2] + hib[nf].x + hjb[nf].x;
            float v3 = a4[3] + hib[nf].y + hjb[nf].y;
            v0 = (v0 > 0.f) ? v0 : 0.01f * v0;
            v1 = (v1 > 0.f) ? v1 : 0.01f * v1;
            v2 = (v2 > 0.f) ? v2 : 0.01f * v2;
            v3 = (v3 > 0.f) ? v3 : 0.01f * v3;
            float a0 = As[n0], a1 = As[n0 + 1];
            p0 += v0 * a0 + v1 * a1;
            p1 += v2 * a0 + v3 * a1;
            if (!lastl)
                fout4[off0 + tl * 128 + nf * 32 + lane] = make_float4(v0, v1, v2, v3);
        }
        p0 += __shfl_xor_sync(0xffffffffu, p0, 1);
        p0 += __shfl_xor_sync(0xffffffffu, p0, 2);
        p1 += __shfl_xor_sync(0xffffffffu, p1, 1);
        p1 += __shfl_xor_sync(0xffffffffu, p1, 2);
        if (t == 0) {
            g_logits[e0] = p0;
            g_logits[e1] = p1;
        }
    }
}

// ---------------- agg (+relu) fused with next layer's projections ----------
// 512-thr blocks (16 nodes); exact trip bound; dual accumulators.
__global__ void k_aggproj(const float* __restrict__ Wni, const float* __restrict__ Wnj,
                          const float* __restrict__ Wn, const float* __restrict__ b,
                          int last) {
    __shared__ float wi[32][32], wj[32][32], wn[32][32], bs[32];
    int tid = threadIdx.x;
    if (!last) {
        for (int i = tid; i < 1024; i += 512) {
            wi[i >> 5][i & 31] = Wni[i];
            wj[i >> 5][i & 31] = Wnj[i];
            wn[i >> 5][i & 31] = Wn[i];
        }
        if (tid < 32) bs[tid] = b[tid];
    }
    __syncthreads();
    int node = blockIdx.x * 16 + (tid >> 5);
    int lane = tid & 31;
    if (node >= NN) return;
    int beg = g_row[node], end = g_row[node + 1];
    int deg = end - beg;
    int full_end = beg + (deg & ~31);
    float s = 0.f, acc0 = 0.f, acc1 = 0.f;
    for (int chunk = beg; chunk < full_end; chunk += 32) {
        float w = __expf(g_logits[chunk + lane]);
        int sv = g_srcS[chunk + lane];
        s += w;
#pragma unroll
        for (int e = 0; e < 32; e += 2) {
            float we0 = __shfl_sync(0xffffffffu, w, e);
            int   se0 = __shfl_sync(0xffffffffu, sv, e);
            float we1 = __shfl_sync(0xffffffffu, w, e + 1);
            int   se1 = __shfl_sync(0xffffffffu, sv, e + 1);
            acc0 += we0 * g_hn[se0 * DD + lane];
            acc1 += we1 * g_hn[se1 * DD + lane];
        }
    }
    int lim = end - full_end;
    if (lim > 0) {
        int i = full_end + lane;
        float w = 0.f;
        int sv = 0;
        if (lane < lim) {
            w = __expf(g_logits[i]);
            sv = g_srcS[i];
        }
        s += w;
        for (int e = 0; e < lim; e++) {
            float we = __shfl_sync(0xffffffffu, w, e);
            int se = __shfl_sync(0xffffffffu, sv, e);
            acc0 += we * g_hn[se * DD + lane];
        }
    }
#pragma unroll
    for (int o = 16; o; o >>= 1) s += __shfl_xor_sync(0xffffffffu, s, o);
    float hv = (deg > 0) ? fmaxf((acc0 + acc1) / s, 0.f) : 0.f;

    if (last) {
        g_h[node * DD + lane] = hv;
        float v = hv;
#pragma unroll
        for (int o = 16; o; o >>= 1) v = fmaxf(v, __shfl_xor_sync(0xffffffffu, v, o));
        if (lane == 0) g_rowmax[node] = v;
    } else {
        float ai = bs[lane], aj = 0.f, an = 0.f;
#pragma unroll
        for (int k = 0; k < 32; k++) {
            float hk = __shfl_sync(0xffffffffu, hv, k);
            ai += hk * wi[k][lane];
            aj += hk * wj[k][lane];
            an += hk * wn[k][lane];
        }
        g_hi[node * DD + lane] = ai;
        g_hj[node * DD + lane] = aj;
        g_hn[node * DD + lane] = an;
    }
}

// ---------------- SortPooling + MLP head ----------------
__global__ void k_head(const float* __restrict__ Wlin, const float* __restrict__ blin,
                       const float* __restrict__ W1, const float* __restrict__ b1,
                       const float* __restrict__ W2, const float* __restrict__ b2,
                       const float* __restrict__ Wc, const float* __restrict__ bc,
                       float* __restrict__ out) {
    __shared__ float wv[8][TOPK];
    __shared__ int   wiids[8][TOPK];
    __shared__ int picked[TOPK];
    __shared__ float xs[TOPK * DD];
    __shared__ float y1[32], y2[32], y3[32];
    int tid = threadIdx.x;
    int wid = tid >> 5, lane = tid & 31;

    float lv[TOPK];
    int   li[TOPK];
#pragma unroll
    for (int k = 0; k < TOPK; k++) { lv[k] = -1e30f; li[k] = 0x7fffffff; }
    for (int i = tid; i < NN; i += 256) {
        float v = g_rowmax[i];
        if (v > lv[TOPK - 1] || (v == lv[TOPK - 1] && i < li[TOPK - 1])) {
            int k = TOPK - 1;
            while (k > 0 && (v > lv[k - 1] || (v == lv[k - 1] && i < li[k - 1]))) {
                lv[k] = lv[k - 1]; li[k] = li[k - 1]; k--;
            }
            lv[k] = v; li[k] = i;
        }
    }
    {
        float mv[TOPK];
        int   mi[TOPK];
#pragma unroll
        for (int k = 0; k < TOPK; k++) { mv[k] = lv[k]; mi[k] = li[k]; }
#pragma unroll
        for (int o = 16; o; o >>= 1) {
            float ov[TOPK];
            int   oi[TOPK];
#pragma unroll
            for (int k = 0; k < TOPK; k++) {
                ov[k] = __shfl_xor_sync(0xffffffffu, mv[k], o);
                oi[k] = __shfl_xor_sync(0xffffffffu, mi[k], o);
            }
            float rv[TOPK];
            int   ri[TOPK];
            int a = 0, c = 0;
#pragma unroll
            for (int k = 0; k < TOPK; k++) {
                bool takeA = (c >= TOPK) ||
                             (a < TOPK && (mv[a] > ov[c] || (mv[a] == ov[c] && mi[a] < oi[c])));
                if (takeA) { rv[k] = mv[a]; ri[k] = mi[a]; a++; }
                else       { rv[k] = ov[c]; ri[k] = oi[c]; c++; }
            }
#pragma unroll
            for (int k = 0; k < TOPK; k++) { mv[k] = rv[k]; mi[k] = ri[k]; }
        }
        if (lane == 0) {
#pragma unroll
            for (int k = 0; k < TOPK; k++) { wv[wid][k] = mv[k]; wiids[wid][k] = mi[k]; }
        }
    }
    __syncthreads();
    if (tid == 0) {
        float fv[TOPK];
        int   fi[TOPK];
#pragma unroll
        for (int k = 0; k < TOPK; k++) { fv[k] = -1e30f; fi[k] = 0x7fffffff; }
        for (int w = 0; w < 8; w++) {
            for (int k = 0; k < TOPK; k++) {
                float v = wv[w][k];
                int   i = wiids[w][k];
                if (v > fv[TOPK - 1] || (v == fv[TOPK - 1] && i < fi[TOPK - 1])) {
                    int k2 = TOPK - 1;
                    while (k2 > 0 && (v > fv[k2 - 1] || (v == fv[k2 - 1] && i < fi[k2 - 1]))) {
                        fv[k2] = fv[k2 - 1]; fi[k2] = fi[k2 - 1]; k2--;
                    }
                    fv[k2] = v; fi[k2] = i;
                }
            }
        }
#pragma unroll
        for (int k = 0; k < TOPK; k++) picked[k] = fi[k];
    }
    __syncthreads();

    if (tid < TOPK) {
        float r[32];
        int n = picked[tid];
        for (int d = 0; d < 32; d++) r[d] = g_h[n * DD + d];
        for (int a = 1; a < 32; a++) {
            float key = r[a];
            int b2_ = a - 1;
            while (b2_ >= 0 && r[b2_] > key) { r[b2_ + 1] = r[b2_]; b2_--; }
            r[b2_ + 1] = key;
        }
        for (int d = 0; d < 32; d++) xs[tid * 32 + d] = r[d];
    }
    __syncthreads();

    if (tid < 32) {
        float a = blin[tid];
        for (int i = 0; i < 256; i++) a += xs[i] * Wlin[i * 32 + tid];
        y1[tid] = fmaxf(a, 0.f);
    }
    __syncthreads();
    if (tid < 32) {
        float a = b1[tid];
        for (int k = 0; k < 32; k++) a += y1[k] * W1[k * 32 + tid];
        y2[tid] = fmaxf(a, 0.f);
    }
    __syncthreads();
    if (tid < 32) {
        float a = b2[tid];
        for (int k = 0; k < 32; k++) a += y2[k] * W2[k * 32 + tid];
        y3[tid] = fmaxf(a, 0.f);
    }
    __syncthreads();
    if (tid < 2) {
        float a = bc[tid];
        for (int k = 0; k < 32; k++) a += y3[k] * Wc[k * 2 + tid];
        out[tid] = a;
    }
}

// ---------------- launch ----------------
extern "C" void kernel_launch(void* const* d_in, const int* in_sizes, int n_in,
                              void* d_out, int out_size) {
    (void)in_sizes; (void)n_in; (void)out_size;
    const int*   h_tok     = (const int*)d_in[0];
    const int*   e_tok     = (const int*)d_in[1];
    const int*   src       = (const int*)d_in[2];
    const int*   dst       = (const int*)d_in[3];
    const float* tok_emb   = (const float*)d_in[4];
    const float* e_tok_emb = (const float*)d_in[5];
    const float* W_ni      = (const float*)d_in[6];
    const float* W_nj      = (const float*)d_in[7];
    const float* W_fij     = (const float*)d_in[8];
    const float* b_edge    = (const float*)d_in[9];
    const float* attn      = (const float*)d_in[10];
    const float* W_node    = (const float*)d_in[11];
    const float* W_lin     = (const float*)d_in[12];
    const float* b_lin     = (const float*)d_in[13];
    const float* W1        = (const float*)d_in[14];
    const float* b1        = (const float*)d_in[15];
    const float* W2        = (const float*)d_in[16];
    const float* b2        = (const float*)d_in[17];
    const float* Wc        = (const float*)d_in[18];
    const float* bc        = (const float*)d_in[19];
    float* out = (float*)d_out;

    const int MB = (EE + 255) / 256;                       // 6250 (32 edges/warp)
    const size_t SM_HDR   = 512 * 16 + 32 * 4;             // bfrag + As = 8320
    const size_t SM_BASE  = SM_HDR + 8 * 256 * 16;         // + stage 32KB = 41088
    const size_t SM_FIRST = SM_HDR + VOCAB * 33 * 4;       // + etab = 21520

    k_hist_init<<<EB + WB, 256>>>(dst, h_tok, tok_emb, W_ni, W_nj, W_node, b_edge);
    k_scan<<<1, 1024>>>();
    k_scatter_gather<<<EB, 256>>>(src, dst, e_tok);

    for (int l = 0; l < NLAYERS; l++) {
        int flags = (l & 1) | ((l == 0) ? 2 : 0) | ((l == NLAYERS - 1) ? 4 : 0);
        k_edge_mma<<<MB, 256, (l == 0) ? SM_FIRST : SM_BASE>>>(
            W_fij + l * 1024, attn + l * 32, e_tok_emb, flags);
        if (l < NLAYERS - 1) {
            k_aggproj<<<AB, 512>>>(W_ni + (l + 1) * 1024, W_nj + (l + 1) * 1024,
                                   W_node + (l + 1) * 1024, b_edge + (l + 1) * 32, 0);
        } else {
            k_aggproj<<<AB, 512>>>(W_ni, W_nj, W_node, b_edge, 1);
        }
    }

    k_head<<<1, 256>>>(W_lin, b_lin, W1, b1, W2, b2, Wc, bc, out);
}

// round 17
// speedup vs baseline: 1.1261x; 1.0020x over previous
#include <cuda_runtime.h>
#include <cuda_bf16.h>

#define NN 50000
#define EE 1600000
#define DD 32
#define NLAYERS 8
#define TOPK 8
#define VOCAB 100

// ---------------- device scratch (static, no allocations) ----------------
__device__ float g_hi[NN*DD];
__device__ float g_hj[NN*DD];
__device__ float g_hn[NN*DD];
__device__ float g_h [NN*DD];
// e/f in MMA C-fragment order (f32) per 16-edge tile
__device__ float4 g_e[EE*8];
__device__ float4 g_f[EE*8];
__device__ float g_logits[EE];
__device__ int   g_srcS[EE];
__device__ int   g_dstS[EE];
__device__ int   g_etokS[EE];
__device__ int   g_hist[NN];       // static zero-init; re-zeroed by k_scan each call
__device__ int   g_row [NN+1];
__device__ int   g_cursor[NN];
__device__ float g_rowmax[NN];

__device__ __forceinline__ unsigned f2tf32(float x) {
    unsigned r;
    asm("cvt.rna.tf32.f32 %0, %1;" : "=r"(r) : "f"(x));
    return r;
}

// truncation split: BIG = low-13-bits-masked (exact tf32), SMALL = exact residual
#define SPLITT(F, B, S) do {                                         \
    unsigned _b = __float_as_uint(F) & 0xffffe000u;                  \
    (B) = _b;                                                        \
    (S) = __float_as_uint((F) - __uint_as_float(_b));                \
} while (0)

#define MMA_TF32(ACC, A0, A1, A2, A3, B0, B1)                                   \
    asm volatile("mma.sync.aligned.m16n8k8.row.col.f32.tf32.tf32.f32 "          \
                 "{%0,%1,%2,%3}, {%4,%5,%6,%7}, {%8,%9}, {%0,%1,%2,%3};"        \
                 : "+f"(ACC[0]), "+f"(ACC[1]), "+f"(ACC[2]), "+f"(ACC[3])       \
                 : "r"(A0), "r"(A1), "r"(A2), "r"(A3), "r"(B0), "r"(B1))

#define EB 6250   // edge blocks (256 thr)
#define WB 6250   // node warp-blocks for init (8 nodes per 256-thr block)
#define AB 3125   // aggproj blocks (16 nodes per 512-thr block)

// ---------------- launch 1: hist (blocks 0..EB-1) + init_proj ----------------
__global__ void k_hist_init(const int* __restrict__ dst,
                            const int* __restrict__ h_tok, const float* __restrict__ tok_emb,
                            const float* __restrict__ Wni, const float* __restrict__ Wnj,
                            const float* __restrict__ Wn, const float* __restrict__ b) {
    if (blockIdx.x < EB) {
        int i = blockIdx.x * 256 + threadIdx.x;
        if (i < EE) atomicAdd(&g_hist[dst[i]], 1);
        return;
    }
    __shared__ float wi[32][32], wj[32][32], wn[32][32], bs[32];
    int tid = threadIdx.x;
    for (int i = tid; i < 1024; i += 256) {
        wi[i >> 5][i & 31] = Wni[i];
        wj[i >> 5][i & 31] = Wnj[i];
        wn[i >> 5][i & 31] = Wn[i];
    }
    if (tid < 32) bs[tid] = b[tid];
    __syncthreads();
    int node = (blockIdx.x - EB) * 8 + (tid >> 5);
    int lane = tid & 31;
    if (node >= NN) return;
    float hv = fmaxf(tok_emb[h_tok[node] * DD + lane], 0.f);
    float ai = bs[lane], aj = 0.f, an = 0.f;
#pragma unroll
    for (int k = 0; k < 32; k++) {
        float hk = __shfl_sync(0xffffffffu, hv, k);
        ai += hk * wi[k][lane];
        aj += hk * wj[k][lane];
        an += hk * wn[k][lane];
    }
    g_hi[node * DD + lane] = ai;
    g_hj[node * DD + lane] = aj;
    g_hn[node * DD + lane] = an;
}

// ---------------- launch 2: scan ----------------
__global__ void k_scan() {
    __shared__ int sm[1024];
    int t = threadIdx.x;
    const int CH = (NN + 1023) / 1024;
    int b0 = t * CH;
    int b1 = min(b0 + CH, NN);
    int sum = 0;
    for (int i = b0; i < b1; i++) sum += g_hist[i];
    sm[t] = sum;
    __syncthreads();
    for (int off = 1; off < 1024; off <<= 1) {
        int v = (t >= off) ? sm[t - off] : 0;
        __syncthreads();
        sm[t] += v;
        __syncthreads();
    }
    int pre = sm[t] - sum;
    for (int i = b0; i < b1; i++) {
        g_row[i] = pre;
        g_cursor[i] = pre;
        pre += g_hist[i];
        g_hist[i] = 0;
    }
    if (t == 1023) g_row[NN] = sm[1023];
}

// ---------------- launch 3: fused scatter+gather ----------------
__global__ void k_scatter_gather(const int* __restrict__ src, const int* __restrict__ dst,
                                 const int* __restrict__ e_tok) {
    int i = blockIdx.x * blockDim.x + threadIdx.x;
    if (i >= EE) return;
    int d = dst[i];
    int p = atomicAdd(&g_cursor[d], 1);
    g_srcS[p] = src[i];
    g_dstS[p] = d;
    g_etokS[p] = e_tok[i];
}

// ---------------- edge kernel: 32 edges/warp, tf32 3-term, truncation split --
// e-tile input AND src/dst indices staged via cp.async at entry (zero register
// cost; latency hidden behind bfrag staging + syncthreads).
// flags: bit0 = swap, bit1 = first (e from token table), bit2 = last (skip f store)
// dyn smem: bfrag[512]f4 (8KB) | As[32]f | sIdx[512]i (2KB) | stage[8][256]f4 (32KB)
//           (layer0 aliases etab[VOCAB*33] over the stage region)
__global__ void __launch_bounds__(256)
k_edge_mma(const float* __restrict__ Wf, const float* __restrict__ attn,
           const float* __restrict__ e_emb, int flags) {
    extern __shared__ float4 dsm[];
    float4* bfragP = dsm;                    // ks*128 + nf*32 + lane
    float*  As     = (float*)(dsm + 512);
    int*    sSrc   = (int*)(As + 32);        // [256]
    int*    sDst   = sSrc + 256;             // [256]
    float4* stageP = (float4*)(sDst + 256);  // [q*256 + tid]
    float*  etab   = (float*)(sDst + 256);   // layer-0 alias
    const int swap = flags & 1, first = flags & 2, lastl = flags & 4;
    int tid = threadIdx.x;
    int warp = tid >> 5;
    int lane = tid & 31;
    int base = (blockIdx.x * 8 + warp) * 32;          // exact: grid*8*32 == EE
    unsigned off0 = (unsigned)(base >> 4) * 128u;     // float4 index of tile0

    const float4* ein4 = (const float4*)(swap ? g_f : g_e);
    float4*       fout4 = (float4*)(swap ? g_e : g_f);

    // stage src/dst indices (contiguous block-wide) via cp.async
    {
        unsigned ss = (unsigned)__cvta_generic_to_shared(&sSrc[tid]);
        unsigned sd = (unsigned)__cvta_generic_to_shared(&sDst[tid]);
        const int* gs = g_srcS + blockIdx.x * 256 + tid;
        const int* gd = g_dstS + blockIdx.x * 256 + tid;
        asm volatile("cp.async.ca.shared.global [%0], [%1], 4;" :: "r"(ss), "l"(gs));
        asm volatile("cp.async.ca.shared.global [%0], [%1], 4;" :: "r"(sd), "l"(gd));
    }
    // issue async e-tile loads (latency hidden behind bfrag staging)
    if (!first) {
        unsigned sdst = (unsigned)__cvta_generic_to_shared(&stageP[tid]);
#pragma unroll
        for (int q = 0; q < 8; q++) {
            const float4* g = ein4 + off0 + (q & 3) * 32 + ((q & 4) ? 128 : 0) + lane;
            asm volatile("cp.async.cg.shared.global [%0], [%1], 16;"
                         :: "r"(sdst + q * 4096), "l"(g));
        }
    }
    asm volatile("cp.async.commit_group;");

#pragma unroll
    for (int e2 = 0; e2 < 2; e2++) {
        int eid = tid + e2 * 256;
        int ks = eid >> 7, nf = (eid >> 5) & 3, ln = eid & 31;
        // k-permuted rows: slot (ln&3) <- col ks*8 + 2*(ln&3); slot +4 <- col +1
        int k0 = ks * 8 + 2 * (ln & 3);
        int n  = nf * 8 + (ln >> 2);
        float b0 = Wf[k0 * 32 + n];
        float b1 = Wf[(k0 + 1) * 32 + n];
        unsigned b0b = f2tf32(b0);
        unsigned b0s = f2tf32(b0 - __uint_as_float(b0b));
        unsigned b1b = f2tf32(b1);
        unsigned b1s = f2tf32(b1 - __uint_as_float(b1b));
        bfragP[ks * 128 + nf * 32 + ln] =
            make_float4(__uint_as_float(b0b), __uint_as_float(b0s),
                        __uint_as_float(b1b), __uint_as_float(b1s));
    }
    if (tid < 32) As[tid] = attn[tid];
    if (first) {
        for (int i = tid; i < VOCAB * DD; i += 256)
            etab[(i >> 5) * 33 + (i & 31)] = e_emb[i];
    }
    asm volatile("cp.async.wait_group 0;");
    __syncthreads();

    int r0 = lane >> 2;
    int t = lane & 3;
    int eA0 = base + r0,      eA1 = eA0 + 8;
    int eB0 = base + 16 + r0, eB1 = eB0 + 8;

    int tA0 = 0, tA1 = 0, tB0 = 0, tB1 = 0;
    if (first) {
        tA0 = g_etokS[eA0] * 33; tA1 = g_etokS[eA1] * 33;
        tB0 = g_etokS[eB0] * 33; tB1 = g_etokS[eB1] * 33;
    }

    float acc[8][4];
#pragma unroll
    for (int nf = 0; nf < 8; nf++)
#pragma unroll
        for (int q = 0; q < 4; q++) acc[nf][q] = 0.f;

#pragma unroll
    for (int ks = 0; ks < 4; ks++) {
        float4 va, vb;   // C-frag order {(r0,2t),(r0,2t+1),(r1,2t),(r1,2t+1)}
        if (first) {
            int c = ks * 8 + 2 * t;
            va.x = etab[tA0 + c]; va.y = etab[tA0 + c + 1];
            va.z = etab[tA1 + c]; va.w = etab[tA1 + c + 1];
            vb.x = etab[tB0 + c]; vb.y = etab[tB0 + c + 1];
            vb.z = etab[tB1 + c]; vb.w = etab[tB1 + c + 1];
        } else {
            va = stageP[ks * 256 + tid];
            vb = stageP[(4 + ks) * 256 + tid];
        }
        unsigned ab0, as0, ab1, as1, ab2, as2, ab3, as3;
        SPLITT(va.x, ab0, as0); SPLITT(va.z, ab1, as1);
        SPLITT(va.y, ab2, as2); SPLITT(va.w, ab3, as3);
        unsigned cb0, cs0, cb1, cs1, cb2, cs2, cb3, cs3;
        SPLITT(vb.x, cb0, cs0); SPLITT(vb.z, cb1, cs1);
        SPLITT(vb.y, cb2, cs2); SPLITT(vb.w, cb3, cs3);
#pragma unroll
        for (int nf = 0; nf < 4; nf++) {
            float4 bv = bfragP[ks * 128 + nf * 32 + lane];
            unsigned b0b = __float_as_uint(bv.x), b0s = __float_as_uint(bv.y);
            unsigned b1b = __float_as_uint(bv.z), b1s = __float_as_uint(bv.w);
            MMA_TF32(acc[nf],     ab0, ab1, ab2, ab3, b0b, b1b);
            MMA_TF32(acc[4 + nf], cb0, cb1, cb2, cb3, b0b, b1b);
            MMA_TF32(acc[nf],     ab0, ab1, ab2, ab3, b0s, b1s);
            MMA_TF32(acc[4 + nf], cb0, cb1, cb2, cb3, b0s, b1s);
            MMA_TF32(acc[nf],     as0, as1, as2, as3, b0b, b1b);
            MMA_TF32(acc[4 + nf], cs0, cs1, cs2, cs3, b0b, b1b);
        }
    }

    // epilogue indices from shared (staged at entry; LDS broadcast)
    int wb = warp * 32;
    int sA0 = sSrc[wb + r0], sA1 = sSrc[wb + r0 + 8];
    int sB0 = sSrc[wb + 16 + r0], sB1 = sSrc[wb + 24 + r0];
    int dA0 = sDst[wb + r0], dA1 = sDst[wb + r0 + 8];
    int dB0 = sDst[wb + 16 + r0], dB1 = sDst[wb + 24 + r0];

    const float2* hi2 = (const float2*)g_hi;
    const float2* hj2 = (const float2*)g_hj;

#pragma unroll
    for (int tl = 0; tl < 2; tl++) {
        int s0 = tl ? sB0 : sA0, s1 = tl ? sB1 : sA1;
        int d0 = tl ? dB0 : dA0, d1 = tl ? dB1 : dA1;
        int e0 = tl ? eB0 : eA0, e1 = tl ? eB1 : eA1;
        float2 hia[4], hja[4], hib[4], hjb[4];
#pragma unroll
        for (int nf = 0; nf < 4; nf++) {
            hia[nf] = hi2[s0 * 16 + nf * 4 + t];
            hja[nf] = hj2[d0 * 16 + nf * 4 + t];
            hib[nf] = hi2[s1 * 16 + nf * 4 + t];
            hjb[nf] = hj2[d1 * 16 + nf * 4 + t];
        }
        float p0 = 0.f, p1 = 0.f;
#pragma unroll
        for (int nf = 0; nf < 4; nf++) {
            int n0 = nf * 8 + t * 2;
            float* a4 = acc[tl * 4 + nf];
            float v0 = a4[0] + hia[nf].x + hja[nf].x;
            float v1 = a4[1] + hia[nf].y + hja[nf].y;
            float v2 = a4[2] + hib[nf].x + hjb[nf].x;
            float v3 = a4[3] + hib[nf].y + hjb[nf].y;
            v0 = (v0 > 0.f) ? v0 : 0.01f * v0;
            v1 = (v1 > 0.f) ? v1 : 0.01f * v1;
            v2 = (v2 > 0.f) ? v2 : 0.01f * v2;
            v3 = (v3 > 0.f) ? v3 : 0.01f * v3;
            float a0 = As[n0], a1 = As[n0 + 1];
            p0 += v0 * a0 + v1 * a1;
            p1 += v2 * a0 + v3 * a1;
            if (!lastl)
                fout4[off0 + tl * 128 + nf * 32 + lane] = make_float4(v0, v1, v2, v3);
        }
        p0 += __shfl_xor_sync(0xffffffffu, p0, 1);
        p0 += __shfl_xor_sync(0xffffffffu, p0, 2);
        p1 += __shfl_xor_sync(0xffffffffu, p1, 1);
        p1 += __shfl_xor_sync(0xffffffffu, p1, 2);
        if (t == 0) {
            g_logits[e0] = p0;
            g_logits[e1] = p1;
        }
    }
}

// ---------------- agg (+relu) fused with next layer's projections ----------
// 512-thr blocks (16 nodes); exact trip bound; dual accumulators;
// L2 prefetch of first chunk before the staging sync.
__global__ void k_aggproj(const float* __restrict__ Wni, const float* __restrict__ Wnj,
                          const float* __restrict__ Wn, const float* __restrict__ b,
                          int last) {
    __shared__ float wi[32][32], wj[32][32], wn[32][32], bs[32];
    int tid = threadIdx.x;
    int node = blockIdx.x * 16 + (tid >> 5);
    int lane = tid & 31;
    int beg = 0, end = 0;
    if (node < NN) {
        beg = g_row[node];
        end = g_row[node + 1];
        if (beg + lane < end) {
            asm volatile("prefetch.global.L2 [%0];" :: "l"(g_logits + beg + lane));
            asm volatile("prefetch.global.L2 [%0];" :: "l"(g_srcS + beg + lane));
        }
    }
    if (!last) {
        for (int i = tid; i < 1024; i += 512) {
            wi[i >> 5][i & 31] = Wni[i];
            wj[i >> 5][i & 31] = Wnj[i];
            wn[i >> 5][i & 31] = Wn[i];
        }
        if (tid < 32) bs[tid] = b[tid];
    }
    __syncthreads();
    if (node >= NN) return;
    int deg = end - beg;
    int full_end = beg + (deg & ~31);
    float s = 0.f, acc0 = 0.f, acc1 = 0.f;
    for (int chunk = beg; chunk < full_end; chunk += 32) {
        float w = __expf(g_logits[chunk + lane]);
        int sv = g_srcS[chunk + lane];
        s += w;
#pragma unroll
        for (int e = 0; e < 32; e += 2) {
            float we0 = __shfl_sync(0xffffffffu, w, e);
            int   se0 = __shfl_sync(0xffffffffu, sv, e);
            float we1 = __shfl_sync(0xffffffffu, w, e + 1);
            int   se1 = __shfl_sync(0xffffffffu, sv, e + 1);
            acc0 += we0 * g_hn[se0 * DD + lane];
            acc1 += we1 * g_hn[se1 * DD + lane];
        }
    }
    int lim = end - full_end;
    if (lim > 0) {
        int i = full_end + lane;
        float w = 0.f;
        int sv = 0;
        if (lane < lim) {
            w = __expf(g_logits[i]);
            sv = g_srcS[i];
        }
        s += w;
        for (int e = 0; e < lim; e++) {
            float we = __shfl_sync(0xffffffffu, w, e);
            int se = __shfl_sync(0xffffffffu, sv, e);
            acc0 += we * g_hn[se * DD + lane];
        }
    }
#pragma unroll
    for (int o = 16; o; o >>= 1) s += __shfl_xor_sync(0xffffffffu, s, o);
    float hv = (deg > 0) ? fmaxf((acc0 + acc1) / s, 0.f) : 0.f;

    if (last) {
        g_h[node * DD + lane] = hv;
        float v = hv;
#pragma unroll
        for (int o = 16; o; o >>= 1) v = fmaxf(v, __shfl_xor_sync(0xffffffffu, v, o));
        if (lane == 0) g_rowmax[node] = v;
    } else {
        float ai = bs[lane], aj = 0.f, an = 0.f;
#pragma unroll
        for (int k = 0; k < 32; k++) {
            float hk = __shfl_sync(0xffffffffu, hv, k);
            ai += hk * wi[k][lane];
            aj += hk * wj[k][lane];
            an += hk * wn[k][lane];
        }
        g_hi[node * DD + lane] = ai;
        g_hj[node * DD + lane] = aj;
        g_hn[node * DD + lane] = an;
    }
}

// ---------------- SortPooling + MLP head ----------------
__global__ void k_head(const float* __restrict__ Wlin, const float* __restrict__ blin,
                       const float* __restrict__ W1, const float* __restrict__ b1,
                       const float* __restrict__ W2, const float* __restrict__ b2,
                       const float* __restrict__ Wc, const float* __restrict__ bc,
                       float* __restrict__ out) {
    __shared__ float wv[8][TOPK];
    __shared__ int   wiids[8][TOPK];
    __shared__ int picked[TOPK];
    __shared__ float xs[TOPK * DD];
    __shared__ float y1[32], y2[32], y3[32];
    int tid = threadIdx.x;
    int wid = tid >> 5, lane = tid & 31;

    float lv[TOPK];
    int   li[TOPK];
#pragma unroll
    for (int k = 0; k < TOPK; k++) { lv[k] = -1e30f; li[k] = 0x7fffffff; }
    for (int i = tid; i < NN; i += 256) {
        float v = g_rowmax[i];
        if (v > lv[TOPK - 1] || (v == lv[TOPK - 1] && i < li[TOPK - 1])) {
            int k = TOPK - 1;
            while (k > 0 && (v > lv[k - 1] || (v == lv[k - 1] && i < li[k - 1]))) {
                lv[k] = lv[k - 1]; li[k] = li[k - 1]; k--;
            }
            lv[k] = v; li[k] = i;
        }
    }
    {
        float mv[TOPK];
        int   mi[TOPK];
#pragma unroll
        for (int k = 0; k < TOPK; k++) { mv[k] = lv[k]; mi[k] = li[k]; }
#pragma unroll
        for (int o = 16; o; o >>= 1) {
            float ov[TOPK];
            int   oi[TOPK];
#pragma unroll
            for (int k = 0; k < TOPK; k++) {
                ov[k] = __shfl_xor_sync(0xffffffffu, mv[k], o);
                oi[k] = __shfl_xor_sync(0xffffffffu, mi[k], o);
            }
            float rv[TOPK];
            int   ri[TOPK];
            int a = 0, c = 0;
#pragma unroll
            for (int k = 0; k < TOPK; k++) {
                bool takeA = (c >= TOPK) ||
                             (a < TOPK && (mv[a] > ov[c] || (mv[a] == ov[c] && mi[a] < oi[c])));
                if (takeA) { rv[k] = mv[a]; ri[k] = mi[a]; a++; }
                else       { rv[k] = ov[c]; ri[k] = oi[c]; c++; }
            }
#pragma unroll
            for (int k = 0; k < TOPK; k++) { mv[k] = rv[k]; mi[k] = ri[k]; }
        }
        if (lane == 0) {
#pragma unroll
            for (int k = 0; k < TOPK; k++) { wv[wid][k] = mv[k]; wiids[wid][k] = mi[k]; }
        }
    }
    __syncthreads();
    if (tid == 0) {
        float fv[TOPK];
        int   fi[TOPK];
#pragma unroll
        for (int k = 0; k < TOPK; k++) { fv[k] = -1e30f; fi[k] = 0x7fffffff; }
        for (int w = 0; w < 8; w++) {
            for (int k = 0; k < TOPK; k++) {
                float v = wv[w][k];
                int   i = wiids[w][k];
                if (v > fv[TOPK - 1] || (v == fv[TOPK - 1] && i < fi[TOPK - 1])) {
                    int k2 = TOPK - 1;
                    while (k2 > 0 && (v > fv[k2 - 1] || (v == fv[k2 - 1] && i < fi[k2 - 1]))) {
                        fv[k2] = fv[k2 - 1]; fi[k2] = fi[k2 - 1]; k2--;
                    }
                    fv[k2] = v; fi[k2] = i;
                }
            }
        }
#pragma unroll
        for (int k = 0; k < TOPK; k++) picked[k] = fi[k];
    }
    __syncthreads();

    if (tid < TOPK) {
        float r[32];
        int n = picked[tid];
        for (int d = 0; d < 32; d++) r[d] = g_h[n * DD + d];
        for (int a = 1; a < 32; a++) {
            float key = r[a];
            int b2_ = a - 1;
            while (b2_ >= 0 && r[b2_] > key) { r[b2_ + 1] = r[b2_]; b2_--; }
            r[b2_ + 1] = key;
        }
        for (int d = 0; d < 32; d++) xs[tid * 32 + d] = r[d];
    }
    __syncthreads();

    if (tid < 32) {
        float a = blin[tid];
        for (int i = 0; i < 256; i++) a += xs[i] * Wlin[i * 32 + tid];
        y1[tid] = fmaxf(a, 0.f);
    }
    __syncthreads();
    if (tid < 32) {
        float a = b1[tid];
        for (int k = 0; k < 32; k++) a += y1[k] * W1[k * 32 + tid];
        y2[tid] = fmaxf(a, 0.f);
    }
    __syncthreads();
    if (tid < 32) {
        float a = b2[tid];
        for (int k = 0; k < 32; k++) a += y2[k] * W2[k * 32 + tid];
        y3[tid] = fmaxf(a, 0.f);
    }
    __syncthreads();
    if (tid < 2) {
        float a = bc[tid];
        for (int k = 0; k < 32; k++) a += y3[k] * Wc[k * 2 + tid];
        out[tid] = a;
    }
}

// ---------------- launch ----------------
extern "C" void kernel_launch(void* const* d_in, const int* in_sizes, int n_in,
                              void* d_out, int out_size) {
    (void)in_sizes; (void)n_in; (void)out_size;
    const int*   h_tok     = (const int*)d_in[0];
    const int*   e_tok     = (const int*)d_in[1];
    const int*   src       = (const int*)d_in[2];
    const int*   dst       = (const int*)d_in[3];
    const float* tok_emb   = (const float*)d_in[4];
    const float* e_tok_emb = (const float*)d_in[5];
    const float* W_ni      = (const float*)d_in[6];
    const float* W_nj      = (const float*)d_in[7];
    const float* W_fij     = (const float*)d_in[8];
    const float* b_edge    = (const float*)d_in[9];
    const float* attn      = (const float*)d_in[10];
    const float* W_node    = (const float*)d_in[11];
    const float* W_lin     = (const float*)d_in[12];
    const float* b_lin     = (const float*)d_in[13];
    const float* W1        = (const float*)d_in[14];
    const float* b1        = (const float*)d_in[15];
    const float* W2        = (const float*)d_in[16];
    const float* b2        = (const float*)d_in[17];
    const float* Wc        = (const float*)d_in[18];
    const float* bc        = (const float*)d_in[19];
    float* out = (float*)d_out;

    const int MB = (EE + 255) / 256;                       // 6250 (32 edges/warp)
    const size_t SM_HDR   = 512 * 16 + 32 * 4 + 512 * 4;   // bfrag + As + sIdx = 10368
    const size_t SM_BASE  = SM_HDR + 8 * 256 * 16;         // + stage 32KB = 43136
    const size_t SM_FIRST = SM_HDR + VOCAB * 33 * 4;       // + etab = 23568

    k_hist_init<<<EB + WB, 256>>>(dst, h_tok, tok_emb, W_ni, W_nj, W_node, b_edge);
    k_scan<<<1, 1024>>>();
    k_scatter_gather<<<EB, 256>>>(src, dst, e_tok);

    for (int l = 0; l < NLAYERS; l++) {
        int flags = (l & 1) | ((l == 0) ? 2 : 0) | ((l == NLAYERS - 1) ? 4 : 0);
        k_edge_mma<<<MB, 256, (l == 0) ? SM_FIRST : SM_BASE>>>(
            W_fij + l * 1024, attn + l * 32, e_tok_emb, flags);
        if (l < NLAYERS - 1) {
            k_aggproj<<<AB, 512>>>(W_ni + (l + 1) * 1024, W_nj + (l + 1) * 1024,
                                   W_node + (l + 1) * 1024, b_edge + (l + 1) * 32, 0);
        } else {
            k_aggproj<<<AB, 512>>>(W_ni, W_nj, W_node, b_edge, 1);
        }
    }

    k_head<<<1, 256>>>(W_lin, b_lin, W1, b1, W2, b2, Wc, bc, out);
}